// round 6
// baseline (speedup 1.0000x reference)
#include <cuda_runtime.h>
#include <cuda_fp16.h>

#define NN 100000
#define NE 1600000
#define HD 64

typedef unsigned long long ull;

// ---------------- scratch (device globals; no allocation allowed) ----------
__device__ int   g_deg[NN];
__device__ float g_inv[NN];
__device__ int   g_off[NN + 1];
__device__ int   g_bsum[128];
__device__ int   g_cnt[NN];
__device__ int   g_csr_src[NE];
__device__ __half2 g_p16[NN * 32];   // projected neighbor features (half2 pairs)
__device__ float g_h1[NN * HD];      // h1, later reused as hp
__device__ float g_h2[NN * HD];
__device__ uint2 g_srct[NN * 32];    // interleaved: {We-pair(half2), Wl-pair(half2)}
__device__ uint2 g_dstt[NN * 32];

__device__ __forceinline__ float tanh_fast(float x) {
    float y;
    asm("tanh.approx.f32 %0, %1;" : "=f"(y) : "f"(x));
    return y;
}

// ---- packed f32x2 helpers ---------------------------------------------------
__device__ __forceinline__ ull f2pack(float x, float y) {
    ull r; asm("mov.b64 %0, {%1, %2};" : "=l"(r) : "f"(x), "f"(y)); return r;
}
__device__ __forceinline__ ull fsplat(float v) {
    ull r; asm("mov.b64 %0, {%1, %1};" : "=l"(r) : "f"(v)); return r;
}
__device__ __forceinline__ float2 f2unpack(ull v) {
    float2 r; asm("mov.b64 {%0, %1}, %2;" : "=f"(r.x), "=f"(r.y) : "l"(v)); return r;
}
#define FMA2(acc, a, b) asm("fma.rn.f32x2 %0, %1, %2, %0;" : "+l"(acc) : "l"(a), "l"(b))
__device__ __forceinline__ ull ADD2(ull a, ull b) {
    ull r; asm("add.rn.f32x2 %0, %1, %2;" : "=l"(r) : "l"(a), "l"(b)); return r;
}

// ---------------- init ------------------------------------------------------
__global__ void k_zero() {
    int i = blockIdx.x * blockDim.x + threadIdx.x;
    int stride = gridDim.x * blockDim.x;
    for (int j = i; j < NN; j += stride) { g_deg[j] = 0; g_cnt[j] = 0; }
    if (i < 128) g_bsum[i] = 0;
}

// ---------------- degree histogram -----------------------------------------
__global__ void k_deg(const int* __restrict__ dst) {
    int e = blockIdx.x * blockDim.x + threadIdx.x;
    if (e < NE) atomicAdd(&g_deg[dst[e]], 1);
}

// ---------------- exclusive scan (3 kernels) --------------------------------
__global__ void k_scan1() {
    __shared__ int sh[1024];
    int tid = threadIdx.x;
    int i = blockIdx.x * 1024 + tid;
    int v = (i < NN) ? g_deg[i] : 0;
    sh[tid] = v;
    __syncthreads();
    for (int o = 1; o < 1024; o <<= 1) {
        int t = (tid >= o) ? sh[tid - o] : 0;
        __syncthreads();
        sh[tid] += t;
        __syncthreads();
    }
    if (i < NN) g_off[i] = sh[tid] - v;
    if (tid == 1023) g_bsum[blockIdx.x] = sh[1023];
}

__global__ void k_scan2(int nb) {
    __shared__ int sh[128];
    int tid = threadIdx.x;
    int v = (tid < nb) ? g_bsum[tid] : 0;
    sh[tid] = v;
    __syncthreads();
    for (int o = 1; o < 128; o <<= 1) {
        int t = (tid >= o) ? sh[tid - o] : 0;
        __syncthreads();
        sh[tid] += t;
        __syncthreads();
    }
    g_bsum[tid] = sh[tid] - v;
    if (tid == 127) g_off[NN] = sh[127];
}

__global__ void k_scan3() {
    int i = blockIdx.x * blockDim.x + threadIdx.x;
    if (i < NN) {
        g_off[i] += g_bsum[i >> 10];
        int d = g_deg[i];
        g_inv[i] = 1.0f / (float)(d > 0 ? d : 1);
    }
}

// ---------------- CSR scatter ------------------------------------------------
__global__ void k_scatter(const int* __restrict__ src, const int* __restrict__ dst) {
    int e = blockIdx.x * blockDim.x + threadIdx.x;
    if (e < NE) {
        int d = dst[e];
        int pos = atomicAdd(&g_cnt[d], 1);
        g_csr_src[g_off[d] + pos] = src[e];
    }
}

// ---------------- p1 = node_feat @ W1n  (4 x 64) -> half2 -------------------
__global__ void k_proj1(const float* __restrict__ nf, const float* __restrict__ W) {
    __shared__ float sW[4 * HD];
    int tid = threadIdx.x;
    sW[tid] = W[tid];
    __syncthreads();
    int idx = blockIdx.x * 256 + tid;
    if (idx >= NN * 32) return;
    int n = idx >> 5, j = idx & 31;
    const float* r = &nf[n * 4];
    float r0 = r[0], r1 = r[1], r2 = r[2], r3 = r[3];
    float v0 = r0 * sW[2*j]   + r1 * sW[64 + 2*j]   + r2 * sW[128 + 2*j]   + r3 * sW[192 + 2*j];
    float v1 = r0 * sW[2*j+1] + r1 * sW[64 + 2*j+1] + r2 * sW[128 + 2*j+1] + r3 * sW[192 + 2*j+1];
    g_p16[idx] = __floats2half2_rn(v0, v1);
}

// ---------------- SAGE layer 1 ----------------------------------------------
__global__ void k_sage1(const float* __restrict__ nf, const float* __restrict__ Ws,
                        const float* __restrict__ b) {
    __shared__ float sW[4 * HD];
    int tid = threadIdx.x;
    sW[tid] = Ws[tid];
    __syncthreads();
    int n = blockIdx.x * 8 + (tid >> 5);
    int l = tid & 31;
    if (n >= NN) return;
    int beg = g_off[n], end = g_off[n + 1];
    float ax = 0.f, ay = 0.f;
    int j = beg;
    for (; j + 4 <= end; j += 4) {
        int s0 = g_csr_src[j], s1 = g_csr_src[j + 1];
        int s2 = g_csr_src[j + 2], s3 = g_csr_src[j + 3];
        float2 q0 = __half22float2(g_p16[s0 * 32 + l]);
        float2 q1 = __half22float2(g_p16[s1 * 32 + l]);
        float2 q2 = __half22float2(g_p16[s2 * 32 + l]);
        float2 q3 = __half22float2(g_p16[s3 * 32 + l]);
        ax += (q0.x + q1.x) + (q2.x + q3.x);
        ay += (q0.y + q1.y) + (q2.y + q3.y);
    }
    for (; j < end; j++) {
        float2 q = __half22float2(g_p16[g_csr_src[j] * 32 + l]);
        ax += q.x; ay += q.y;
    }
    float iv = g_inv[n];
    const float* r = &nf[n * 4];
    float n0 = r[0], n1 = r[1], n2 = r[2], n3 = r[3];
    float sx = n0*sW[2*l]   + n1*sW[64+2*l]   + n2*sW[128+2*l]   + n3*sW[192+2*l];
    float sy = n0*sW[2*l+1] + n1*sW[64+2*l+1] + n2*sW[128+2*l+1] + n3*sW[192+2*l+1];
    float2 o;
    o.x = fmaxf(sx + ax * iv + b[2*l],     0.f);
    o.y = fmaxf(sy + ay * iv + b[2*l+1],   0.f);
    *(float2*)&g_h1[(size_t)n * HD + 2*l] = o;
}

// ---- dual 64x64 GEMM, FFMA2, 4 nodes/warp: p2=h1@Wn (half2), t=h1@Ws (f32) --
__global__ void k_gemm2x(const float* __restrict__ in, const float* __restrict__ Wn,
                         const float* __restrict__ Ws, float* __restrict__ outf) {
    __shared__ float sWa[HD * HD];          // 16 KB  (Wn)
    __shared__ float sWb[HD * HD];          // 16 KB  (Ws)
    __shared__ ull   sh2[8][4 * HD];        // 16 KB  duplicated h pairs
    int tid = threadIdx.x, w = tid >> 5, l = tid & 31;
    for (int i = tid; i < HD * HD; i += 256) { sWa[i] = Wn[i]; sWb[i] = Ws[i]; }
    int nbase = blockIdx.x * 32 + w * 4;
    int lim = (NN - nbase) * HD;
    const float* src = in + (size_t)nbase * HD;
    for (int t = l; t < 4 * HD; t += 32) {
        float v = (t < lim) ? src[t] : 0.f;
        sh2[w][t] = fsplat(v);
    }
    __syncthreads();
    if (nbase >= NN) return;
    ull aa[4], ab[4];
#pragma unroll
    for (int i = 0; i < 4; i++) { aa[i] = 0ull; ab[i] = 0ull; }
#pragma unroll 8
    for (int k = 0; k < HD; k += 2) {
        ull wa0 = *(const ull*)&sWa[k * HD + 2 * l];
        ull wb0 = *(const ull*)&sWb[k * HD + 2 * l];
        ull wa1 = *(const ull*)&sWa[(k + 1) * HD + 2 * l];
        ull wb1 = *(const ull*)&sWb[(k + 1) * HD + 2 * l];
#pragma unroll
        for (int i = 0; i < 4; i++) {
            ulonglong2 h = *(const ulonglong2*)&sh2[w][i * HD + k];
            FMA2(aa[i], h.x, wa0);
            FMA2(ab[i], h.x, wb0);
            FMA2(aa[i], h.y, wa1);
            FMA2(ab[i], h.y, wb1);
        }
    }
#pragma unroll
    for (int i = 0; i < 4; i++) {
        int n = nbase + i;
        if (n < NN) {
            float2 pa = f2unpack(aa[i]);
            g_p16[(size_t)n * 32 + l] = __floats2half2_rn(pa.x, pa.y);
            float2 pb = f2unpack(ab[i]);
            *(float2*)&outf[(size_t)n * HD + 2 * l] = pb;
        }
    }
}

// ---- single 64x64 GEMM, FFMA2, 8 nodes/warp, bias+relu ---------------------
__global__ void k_gemm8f(const float* __restrict__ in, const float* __restrict__ W,
                         const float* __restrict__ bias, float* __restrict__ out) {
    __shared__ float sW[HD * HD];           // 16 KB
    __shared__ ull   sh2[8][8 * HD];        // 32 KB
    int tid = threadIdx.x, w = tid >> 5, l = tid & 31;
    for (int i = tid; i < HD * HD; i += 256) sW[i] = W[i];
    int nbase = blockIdx.x * 64 + w * 8;
    int lim = (NN - nbase) * HD;
    const float* src = in + (size_t)nbase * HD;
    for (int t = l; t < 8 * HD; t += 32) {
        float v = (t < lim) ? src[t] : 0.f;
        sh2[w][t] = fsplat(v);
    }
    __syncthreads();
    if (nbase >= NN) return;
    ull bp = f2pack(bias[2 * l], bias[2 * l + 1]);
    ull acc[8];
#pragma unroll
    for (int i = 0; i < 8; i++) acc[i] = bp;
#pragma unroll 8
    for (int k = 0; k < HD; k += 2) {
        ull w0 = *(const ull*)&sW[k * HD + 2 * l];
        ull w1 = *(const ull*)&sW[(k + 1) * HD + 2 * l];
#pragma unroll
        for (int i = 0; i < 8; i++) {
            ulonglong2 h = *(const ulonglong2*)&sh2[w][i * HD + k];
            FMA2(acc[i], h.x, w0);
            FMA2(acc[i], h.y, w1);
        }
    }
#pragma unroll
    for (int i = 0; i < 8; i++) {
        int n = nbase + i;
        if (n < NN) {
            float2 p = f2unpack(acc[i]);
            p.x = fmaxf(p.x, 0.f); p.y = fmaxf(p.y, 0.f);
            *(float2*)&out[(size_t)n * HD + 2 * l] = p;
        }
    }
}

// ---------------- SAGE layer 2 combine: h2 = relu(h2 + agg*inv + b2) --------
__global__ void k_sage2b(const float* __restrict__ b) {
    int tid = threadIdx.x;
    int n = blockIdx.x * 8 + (tid >> 5);
    int l = tid & 31;
    if (n >= NN) return;
    int beg = g_off[n], end = g_off[n + 1];
    float ax = 0.f, ay = 0.f;
    int j = beg;
    for (; j + 4 <= end; j += 4) {
        int s0 = g_csr_src[j], s1 = g_csr_src[j + 1];
        int s2 = g_csr_src[j + 2], s3 = g_csr_src[j + 3];
        float2 q0 = __half22float2(g_p16[s0 * 32 + l]);
        float2 q1 = __half22float2(g_p16[s1 * 32 + l]);
        float2 q2 = __half22float2(g_p16[s2 * 32 + l]);
        float2 q3 = __half22float2(g_p16[s3 * 32 + l]);
        ax += (q0.x + q1.x) + (q2.x + q3.x);
        ay += (q0.y + q1.y) + (q2.y + q3.y);
    }
    for (; j < end; j++) {
        float2 q = __half22float2(g_p16[g_csr_src[j] * 32 + l]);
        ax += q.x; ay += q.y;
    }
    float iv = g_inv[n];
    float2 t = *(const float2*)&g_h2[(size_t)n * HD + 2 * l];
    float2 o;
    o.x = fmaxf(t.x + ax * iv + b[2 * l],     0.f);
    o.y = fmaxf(t.y + ay * iv + b[2 * l + 1], 0.f);
    *(float2*)&g_h2[(size_t)n * HD + 2 * l] = o;
}

// ---- dual table GEMM, FFMA2, 4 nodes/warp -> interleaved half2 tables ------
__global__ void k_tab2x(const float* __restrict__ hp, const float* __restrict__ Wa,
                        const float* __restrict__ Wb, uint2* __restrict__ tab) {
    __shared__ float sWa[HD * HD];          // 16 KB
    __shared__ float sWb[HD * HD];          // 16 KB
    __shared__ ull   sh2[8][4 * HD];        // 16 KB
    int tid = threadIdx.x, w = tid >> 5, l = tid & 31;
    for (int i = tid; i < HD * HD; i += 256) { sWa[i] = Wa[i]; sWb[i] = Wb[i]; }
    int nbase = blockIdx.x * 32 + w * 4;
    int lim = (NN - nbase) * HD;
    const float* src = hp + (size_t)nbase * HD;
    for (int t = l; t < 4 * HD; t += 32) {
        float v = (t < lim) ? src[t] : 0.f;
        sh2[w][t] = fsplat(v);
    }
    __syncthreads();
    if (nbase >= NN) return;
    ull aa[4], ab[4];
#pragma unroll
    for (int i = 0; i < 4; i++) { aa[i] = 0ull; ab[i] = 0ull; }
#pragma unroll 8
    for (int k = 0; k < HD; k += 2) {
        ull wa0 = *(const ull*)&sWa[k * HD + 2 * l];
        ull wb0 = *(const ull*)&sWb[k * HD + 2 * l];
        ull wa1 = *(const ull*)&sWa[(k + 1) * HD + 2 * l];
        ull wb1 = *(const ull*)&sWb[(k + 1) * HD + 2 * l];
#pragma unroll
        for (int i = 0; i < 4; i++) {
            ulonglong2 h = *(const ulonglong2*)&sh2[w][i * HD + k];
            FMA2(aa[i], h.x, wa0);
            FMA2(ab[i], h.x, wb0);
            FMA2(aa[i], h.y, wa1);
            FMA2(ab[i], h.y, wb1);
        }
    }
#pragma unroll
    for (int i = 0; i < 4; i++) {
        int n = nbase + i;
        if (n < NN) {
            float2 pa = f2unpack(aa[i]);
            float2 pb = f2unpack(ab[i]);
            __half2 ha = __floats2half2_rn(pa.x, pa.y);
            __half2 hb = __floats2half2_rn(pb.x, pb.y);
            uint2 v;
            v.x = *(unsigned int*)&ha;
            v.y = *(unsigned int*)&hb;
            tab[(size_t)n * 32 + l] = v;
        }
    }
}

// ---------------- edge kernel: persistent warps, register weights -----------
__global__ void k_edge(const int* __restrict__ src, const int* __restrict__ dst,
                       const float* __restrict__ ef,
                       const float* __restrict__ We1, const float* __restrict__ be1,
                       const float* __restrict__ We2, const float* __restrict__ be2,
                       const float* __restrict__ Wl1, const float* __restrict__ bl1,
                       const float* __restrict__ Wl2, const float* __restrict__ bl2,
                       float* __restrict__ out) {
    int l = threadIdx.x & 31;
    int warp = (blockIdx.x * blockDim.x + threadIdx.x) >> 5;
    int nw = (gridDim.x * blockDim.x) >> 5;

    ull we5[5], wl5[5];
#pragma unroll
    for (int k = 0; k < 5; k++) {
        float2 a = *(const float2*)&We1[(128 + k) * HD + 2 * l];
        float2 b = *(const float2*)&Wl1[(128 + k) * HD + 2 * l];
        we5[k] = f2pack(a.x, a.y);
        wl5[k] = f2pack(b.x, b.y);
    }
    ull be1p = f2pack(be1[2*l], be1[2*l+1]);
    float bl1x = bl1[2*l], bl1y = bl1[2*l+1];
    float we2x = We2[2*l], we2y = We2[2*l+1];
    float wl2x = Wl2[2*l], wl2y = Wl2[2*l+1];
    float be2v = be2[0],   bl2v = bl2[0];

    for (int e = warp; e < NE; e += nw) {
        int s = __ldg(&src[e]);
        int d = __ldg(&dst[e]);
        uint2 ts = g_srct[(size_t)s * 32 + l];
        uint2 td = g_dstt[(size_t)d * 32 + l];
        float efl = (l < 5) ? __ldg(&ef[(size_t)e * 5 + l]) : 0.f;

        float2 a  = __half22float2(*(__half2*)&ts.x);
        float2 av = __half22float2(*(__half2*)&ts.y);
        float2 b  = __half22float2(*(__half2*)&td.x);
        float2 bv = __half22float2(*(__half2*)&td.y);

        ull u = ADD2(ADD2(f2pack(a.x, a.y), f2pack(b.x, b.y)), be1p);
        ull v = ADD2(f2pack(av.x, av.y), f2pack(bv.x, bv.y));
#pragma unroll
        for (int k = 0; k < 5; k++) {
            ull eks = fsplat(__shfl_sync(0xffffffffu, efl, k));
            FMA2(u, eks, we5[k]);
            FMA2(v, eks, wl5[k]);
        }
        float2 up = f2unpack(u);
        float part = tanh_fast(up.x) * we2x + tanh_fast(up.y) * we2y;
#pragma unroll
        for (int o = 16; o > 0; o >>= 1) part += __shfl_xor_sync(0xffffffffu, part, o);
        float wgt = 1.f / (1.f + __expf(-(part + be2v)));
        float2 vp = f2unpack(v);
        float o0 = fmaxf(fmaf(wgt, vp.x, bl1x), 0.f);
        float o1 = fmaxf(fmaf(wgt, vp.y, bl1y), 0.f);
        float p2 = o0 * wl2x + o1 * wl2y;
#pragma unroll
        for (int o = 16; o > 0; o >>= 1) p2 += __shfl_xor_sync(0xffffffffu, p2, o);
        if (l == 0) out[e] = p2 + bl2v;
    }
}

// ---------------- launch -----------------------------------------------------
extern "C" void kernel_launch(void* const* d_in, const int* in_sizes, int n_in,
                              void* d_out, int out_size) {
    const float* node_feat = (const float*)d_in[0];
    const float* edge_feat = (const float*)d_in[1];
    const int*   src       = (const int*)d_in[2];
    const int*   dst       = (const int*)d_in[3];
    const float* W1s = (const float*)d_in[4];
    const float* W1n = (const float*)d_in[5];
    const float* b1  = (const float*)d_in[6];
    const float* W2s = (const float*)d_in[7];
    const float* W2n = (const float*)d_in[8];
    const float* b2  = (const float*)d_in[9];
    const float* Wnp = (const float*)d_in[10];
    const float* bnp = (const float*)d_in[11];
    const float* We1 = (const float*)d_in[12];
    const float* be1 = (const float*)d_in[13];
    const float* We2 = (const float*)d_in[14];
    const float* be2 = (const float*)d_in[15];
    const float* Wl1 = (const float*)d_in[16];
    const float* bl1 = (const float*)d_in[17];
    const float* Wl2 = (const float*)d_in[18];
    const float* bl2 = (const float*)d_in[19];
    float* out = (float*)d_out;

    float *ph1, *ph2;
    uint2 *pst, *pdt;
    cudaGetSymbolAddress((void**)&ph1, g_h1);
    cudaGetSymbolAddress((void**)&ph2, g_h2);
    cudaGetSymbolAddress((void**)&pst, g_srct);
    cudaGetSymbolAddress((void**)&pdt, g_dstt);

    int nb   = (NN + 1023) / 1024;
    int nblk = (NN + 7) / 8;          // warp-per-node kernels
    int g4   = (NN + 31) / 32;        // 4-node/warp dual-GEMM kernels
    int g8   = (NN + 63) / 64;        // 8-node/warp single-GEMM kernel

    k_zero<<<512, 256>>>();
    k_deg<<<(NE + 255) / 256, 256>>>(dst);
    k_scan1<<<nb, 1024>>>();
    k_scan2<<<1, 128>>>(nb);
    k_scan3<<<(NN + 255) / 256, 256>>>();
    k_scatter<<<(NE + 255) / 256, 256>>>(src, dst);

    // Layer 1
    k_proj1<<<(NN * 32 + 255) / 256, 256>>>(node_feat, W1n);
    k_sage1<<<nblk, 256>>>(node_feat, W1s, b1);

    // Layer 2: p2 = h1@W2n (half2) AND t = h1@W2s (fp32) in one pass
    k_gemm2x<<<g4, 256>>>(ph1, W2n, W2s, ph2);
    k_sage2b<<<nblk, 256>>>(b2);

    // hp = relu(h2@Wnp + bnp) into g_h1
    k_gemm8f<<<g8, 256>>>(ph2, Wnp, bnp, ph1);

    // per-node interleaved half2 tables
    k_tab2x<<<g4, 256>>>(ph1, We1,           Wl1,           pst); // src-role rows 0..63
    k_tab2x<<<g4, 256>>>(ph1, We1 + 64 * HD, Wl1 + 64 * HD, pdt); // dst-role rows 64..127

    // persistent fused edge stage
    k_edge<<<1184, 256>>>(src, dst, edge_feat,
                          We1, be1, We2, be2, Wl1, bl1, Wl2, bl2, out);
}

// round 7
// speedup vs baseline: 1.1433x; 1.1433x over previous
#include <cuda_runtime.h>
#include <cuda_fp16.h>

#define NN 100000
#define NE 1600000
#define HD 64

// ---------------- scratch (device globals; no allocation allowed) ----------
__device__ int   g_deg[NN];
__device__ float g_inv[NN];
__device__ int   g_off[NN + 1];
__device__ int   g_bsum[128];
__device__ int   g_cnt[NN];
__device__ int   g_csr_src[NE];
__device__ __half2 g_p16[NN * 32];   // projected neighbor features (half2 pairs)
__device__ float g_h1[NN * HD];      // h1, later reused as hp
__device__ float g_h2[NN * HD];
// per-node tables, 16B-aligned: 16 x uint4 per node; as uint2[32]:
// idx j = {We-pair(feats 2j,2j+1) , Wl-pair} interleaved
__device__ uint4 g_srct[NN * 16];
__device__ uint4 g_dstt[NN * 16];

__device__ __forceinline__ float tanh_fast(float x) {
    float y;
    asm("tanh.approx.f32 %0, %1;" : "=f"(y) : "f"(x));
    return y;
}

// ---------------- degree histogram -----------------------------------------
__global__ void k_deg(const int* __restrict__ dst) {
    int e = blockIdx.x * blockDim.x + threadIdx.x;
    if (e < NE) atomicAdd(&g_deg[dst[e]], 1);
}

// ---------------- exclusive scan (3 kernels) --------------------------------
__global__ void k_scan1() {
    __shared__ int sh[1024];
    int tid = threadIdx.x;
    int i = blockIdx.x * 1024 + tid;
    int v = (i < NN) ? g_deg[i] : 0;
    sh[tid] = v;
    __syncthreads();
    for (int o = 1; o < 1024; o <<= 1) {
        int t = (tid >= o) ? sh[tid - o] : 0;
        __syncthreads();
        sh[tid] += t;
        __syncthreads();
    }
    if (i < NN) g_off[i] = sh[tid] - v;
    if (tid == 1023) g_bsum[blockIdx.x] = sh[1023];
}

__global__ void k_scan2(int nb) {
    __shared__ int sh[128];
    int tid = threadIdx.x;
    int v = (tid < nb) ? g_bsum[tid] : 0;
    sh[tid] = v;
    __syncthreads();
    for (int o = 1; o < 128; o <<= 1) {
        int t = (tid >= o) ? sh[tid - o] : 0;
        __syncthreads();
        sh[tid] += t;
        __syncthreads();
    }
    g_bsum[tid] = sh[tid] - v;
    if (tid == 127) g_off[NN] = sh[127];
}

__global__ void k_scan3() {
    int i = blockIdx.x * blockDim.x + threadIdx.x;
    if (i < NN) {
        g_off[i] += g_bsum[i >> 10];
        int d = g_deg[i];
        g_inv[i] = 1.0f / (float)(d > 0 ? d : 1);
    }
}

// ---------------- CSR scatter ------------------------------------------------
__global__ void k_scatter(const int* __restrict__ src, const int* __restrict__ dst) {
    int e = blockIdx.x * blockDim.x + threadIdx.x;
    if (e < NE) {
        int d = dst[e];
        int pos = atomicAdd(&g_cnt[d], 1);
        g_csr_src[g_off[d] + pos] = src[e];
    }
}

// ---------------- p1 = node_feat @ W1n  (4 x 64) -> half2 -------------------
__global__ void k_proj1(const float* __restrict__ nf, const float* __restrict__ W) {
    __shared__ float sW[4 * HD];
    int tid = threadIdx.x;
    sW[tid] = W[tid];
    __syncthreads();
    int idx = blockIdx.x * 256 + tid;
    if (idx >= NN * 32) return;
    int n = idx >> 5, j = idx & 31;
    const float* r = &nf[n * 4];
    float r0 = r[0], r1 = r[1], r2 = r[2], r3 = r[3];
    float v0 = r0 * sW[2*j]   + r1 * sW[64 + 2*j]   + r2 * sW[128 + 2*j]   + r3 * sW[192 + 2*j];
    float v1 = r0 * sW[2*j+1] + r1 * sW[64 + 2*j+1] + r2 * sW[128 + 2*j+1] + r3 * sW[192 + 2*j+1];
    g_p16[idx] = __floats2half2_rn(v0, v1);
}

// ---------------- SAGE layer 1 ----------------------------------------------
__global__ void k_sage1(const float* __restrict__ nf, const float* __restrict__ Ws,
                        const float* __restrict__ b) {
    __shared__ float sW[4 * HD];
    int tid = threadIdx.x;
    sW[tid] = Ws[tid];
    __syncthreads();
    int n = blockIdx.x * 8 + (tid >> 5);
    int l = tid & 31;
    if (n >= NN) return;
    int beg = g_off[n], end = g_off[n + 1];
    float ax = 0.f, ay = 0.f;
    int j = beg;
    for (; j + 4 <= end; j += 4) {
        int s0 = g_csr_src[j], s1 = g_csr_src[j + 1];
        int s2 = g_csr_src[j + 2], s3 = g_csr_src[j + 3];
        float2 q0 = __half22float2(g_p16[s0 * 32 + l]);
        float2 q1 = __half22float2(g_p16[s1 * 32 + l]);
        float2 q2 = __half22float2(g_p16[s2 * 32 + l]);
        float2 q3 = __half22float2(g_p16[s3 * 32 + l]);
        ax += (q0.x + q1.x) + (q2.x + q3.x);
        ay += (q0.y + q1.y) + (q2.y + q3.y);
    }
    for (; j < end; j++) {
        float2 q = __half22float2(g_p16[g_csr_src[j] * 32 + l]);
        ax += q.x; ay += q.y;
    }
    float iv = g_inv[n];
    const float* r = &nf[n * 4];
    float n0 = r[0], n1 = r[1], n2 = r[2], n3 = r[3];
    float sx = n0*sW[2*l]   + n1*sW[64+2*l]   + n2*sW[128+2*l]   + n3*sW[192+2*l];
    float sy = n0*sW[2*l+1] + n1*sW[64+2*l+1] + n2*sW[128+2*l+1] + n3*sW[192+2*l+1];
    float2 o;
    o.x = fmaxf(sx + ax * iv + b[2*l],     0.f);
    o.y = fmaxf(sy + ay * iv + b[2*l+1],   0.f);
    *(float2*)&g_h1[(size_t)n * HD + 2*l] = o;
}

// ---- fused dual GEMM (scalar), 8 nodes/warp: p2=h1@Wn -> half2, h1@Ws -> f32
__global__ void k_gemm2s(const float* __restrict__ in, const float* __restrict__ Wn,
                         const float* __restrict__ Ws, float* __restrict__ outf) {
    __shared__ float sWa[HD * HD];          // 16 KB
    __shared__ float sWb[HD * HD];          // 16 KB
    __shared__ float sh[8][8 * HD];         // 16 KB
    int tid = threadIdx.x, w = tid >> 5, l = tid & 31;
    for (int i = tid; i < HD * HD; i += 256) { sWa[i] = Wn[i]; sWb[i] = Ws[i]; }
    int nbase = blockIdx.x * 64 + w * 8;
    int lim = (NN - nbase) * HD;
    const float* src = in + (size_t)nbase * HD;
    for (int t = l; t < 8 * HD; t += 32) if (t < lim) sh[w][t] = src[t];
    __syncthreads();
    if (nbase >= NN) return;
    float2 aa[8], ab[8];
#pragma unroll
    for (int i = 0; i < 8; i++) { aa[i] = make_float2(0.f, 0.f); ab[i] = make_float2(0.f, 0.f); }
#pragma unroll 4
    for (int k = 0; k < HD; k++) {
        float2 wa = *(const float2*)&sWa[k * HD + 2 * l];
        float2 wb = *(const float2*)&sWb[k * HD + 2 * l];
#pragma unroll
        for (int i = 0; i < 8; i++) {
            float hk = sh[w][i * HD + k];
            aa[i].x = fmaf(hk, wa.x, aa[i].x);
            aa[i].y = fmaf(hk, wa.y, aa[i].y);
            ab[i].x = fmaf(hk, wb.x, ab[i].x);
            ab[i].y = fmaf(hk, wb.y, ab[i].y);
        }
    }
#pragma unroll
    for (int i = 0; i < 8; i++) {
        int n = nbase + i;
        if (n < NN) {
            g_p16[(size_t)n * 32 + l] = __floats2half2_rn(aa[i].x, aa[i].y);
            *(float2*)&outf[(size_t)n * HD + 2 * l] = ab[i];
        }
    }
}

// ---- single 64x64 GEMM (scalar), 8 nodes/warp, bias + relu -----------------
__global__ void k_gemm8f(const float* __restrict__ in, const float* __restrict__ W,
                         const float* __restrict__ bias, float* __restrict__ out) {
    __shared__ float sW[HD * HD];
    __shared__ float sh[8][8 * HD];
    int tid = threadIdx.x, w = tid >> 5, l = tid & 31;
    for (int i = tid; i < HD * HD; i += 256) sW[i] = W[i];
    int nbase = blockIdx.x * 64 + w * 8;
    int lim = (NN - nbase) * HD;
    const float* src = in + (size_t)nbase * HD;
    for (int t = l; t < 8 * HD; t += 32) if (t < lim) sh[w][t] = src[t];
    __syncthreads();
    if (nbase >= NN) return;
    float2 acc[8];
#pragma unroll
    for (int i = 0; i < 8; i++) acc[i] = make_float2(0.f, 0.f);
#pragma unroll 8
    for (int k = 0; k < HD; k++) {
        float2 wv = *(const float2*)&sW[k * HD + 2 * l];
#pragma unroll
        for (int i = 0; i < 8; i++) {
            float hk = sh[w][i * HD + k];
            acc[i].x = fmaf(hk, wv.x, acc[i].x);
            acc[i].y = fmaf(hk, wv.y, acc[i].y);
        }
    }
    float bx = bias[2 * l], by = bias[2 * l + 1];
#pragma unroll
    for (int i = 0; i < 8; i++) {
        int n = nbase + i;
        if (n < NN) {
            float ox = fmaxf(acc[i].x + bx, 0.f);
            float oy = fmaxf(acc[i].y + by, 0.f);
            *(float2*)&out[(size_t)n * HD + 2 * l] = make_float2(ox, oy);
        }
    }
}

// ---------------- SAGE layer 2 combine: h2 = relu(h2 + agg*inv + b2) --------
__global__ void k_sage2b(const float* __restrict__ b) {
    int tid = threadIdx.x;
    int n = blockIdx.x * 8 + (tid >> 5);
    int l = tid & 31;
    if (n >= NN) return;
    int beg = g_off[n], end = g_off[n + 1];
    float ax = 0.f, ay = 0.f;
    int j = beg;
    for (; j + 4 <= end; j += 4) {
        int s0 = g_csr_src[j], s1 = g_csr_src[j + 1];
        int s2 = g_csr_src[j + 2], s3 = g_csr_src[j + 3];
        float2 q0 = __half22float2(g_p16[s0 * 32 + l]);
        float2 q1 = __half22float2(g_p16[s1 * 32 + l]);
        float2 q2 = __half22float2(g_p16[s2 * 32 + l]);
        float2 q3 = __half22float2(g_p16[s3 * 32 + l]);
        ax += (q0.x + q1.x) + (q2.x + q3.x);
        ay += (q0.y + q1.y) + (q2.y + q3.y);
    }
    for (; j < end; j++) {
        float2 q = __half22float2(g_p16[g_csr_src[j] * 32 + l]);
        ax += q.x; ay += q.y;
    }
    float iv = g_inv[n];
    float2 t = *(const float2*)&g_h2[(size_t)n * HD + 2 * l];
    float2 o;
    o.x = fmaxf(t.x + ax * iv + b[2 * l],     0.f);
    o.y = fmaxf(t.y + ay * iv + b[2 * l + 1], 0.f);
    *(float2*)&g_h2[(size_t)n * HD + 2 * l] = o;
}

// -------- tables (scalar dual GEMM, 8 nodes/warp) -> interleaved half2 ------
__global__ void k_tabk(const float* __restrict__ hp, const float* __restrict__ Wa,
                       const float* __restrict__ Wb, uint2* __restrict__ tab) {
    __shared__ float sWa[HD * HD];
    __shared__ float sWb[HD * HD];
    __shared__ float sh[8][8 * HD];
    int tid = threadIdx.x, w = tid >> 5, l = tid & 31;
    for (int i = tid; i < HD * HD; i += 256) { sWa[i] = Wa[i]; sWb[i] = Wb[i]; }
    int nbase = blockIdx.x * 64 + w * 8;
    int lim = (NN - nbase) * HD;
    const float* src = hp + (size_t)nbase * HD;
    for (int t = l; t < 8 * HD; t += 32) if (t < lim) sh[w][t] = src[t];
    __syncthreads();
    if (nbase >= NN) return;
    float2 aa[8], ab[8];
#pragma unroll
    for (int i = 0; i < 8; i++) { aa[i] = make_float2(0.f, 0.f); ab[i] = make_float2(0.f, 0.f); }
#pragma unroll 4
    for (int k = 0; k < HD; k++) {
        float2 wa = *(const float2*)&sWa[k * HD + 2 * l];
        float2 wb = *(const float2*)&sWb[k * HD + 2 * l];
#pragma unroll
        for (int i = 0; i < 8; i++) {
            float hk = sh[w][i * HD + k];
            aa[i].x = fmaf(hk, wa.x, aa[i].x);
            aa[i].y = fmaf(hk, wa.y, aa[i].y);
            ab[i].x = fmaf(hk, wb.x, ab[i].x);
            ab[i].y = fmaf(hk, wb.y, ab[i].y);
        }
    }
#pragma unroll
    for (int i = 0; i < 8; i++) {
        int n = nbase + i;
        if (n < NN) {
            __half2 ha = __floats2half2_rn(aa[i].x, aa[i].y);
            __half2 hb = __floats2half2_rn(ab[i].x, ab[i].y);
            uint2 v;
            v.x = *(unsigned int*)&ha;
            v.y = *(unsigned int*)&hb;
            tab[(size_t)n * 32 + l] = v;
        }
    }
}

// ------- edge kernel: 16 lanes/edge, 2 edges/warp, persistent ----------------
__global__ void k_edge(const int* __restrict__ src, const int* __restrict__ dst,
                       const float* __restrict__ ef,
                       const float* __restrict__ We1, const float* __restrict__ be1,
                       const float* __restrict__ We2, const float* __restrict__ be2,
                       const float* __restrict__ Wl1, const float* __restrict__ bl1,
                       const float* __restrict__ Wl2, const float* __restrict__ bl2,
                       float* __restrict__ out) {
    int tid = threadIdx.x;
    int l = tid & 31;
    int li = l & 15;            // lane within 16-lane edge group
    int g = l >> 4;             // which of the 2 edges
    int base = l & 16;          // shfl base for my group
    int warp = (blockIdx.x * blockDim.x + tid) >> 5;
    int nw = (gridDim.x * blockDim.x) >> 5;

    // per-lane weights: feats 4*li .. 4*li+3
    float4 we5[5], wl5[5];
#pragma unroll
    for (int k = 0; k < 5; k++) {
        we5[k] = *(const float4*)&We1[(128 + k) * HD + 4 * li];
        wl5[k] = *(const float4*)&Wl1[(128 + k) * HD + 4 * li];
    }
    float4 be1v = *(const float4*)&be1[4 * li];
    float4 bl1v = *(const float4*)&bl1[4 * li];
    float4 we2v = *(const float4*)&We2[4 * li];
    float4 wl2v = *(const float4*)&Wl2[4 * li];
    float be2v = be2[0], bl2v = bl2[0];

    for (int eb = warp * 2; eb < NE; eb += 2 * nw) {
        int e = eb + g;
        int s = __ldg(&src[e]);
        int d = __ldg(&dst[e]);
        uint4 ts = *(const uint4*)((const uint2*)&g_srct[(size_t)s * 16] + 2 * li);
        uint4 td = *(const uint4*)((const uint2*)&g_dstt[(size_t)d * 16] + 2 * li);
        float efl = (li < 5) ? __ldg(&ef[(size_t)e * 5 + li]) : 0.f;

        float2 a0  = __half22float2(*(__half2*)&ts.x);   // We feats 4li,4li+1
        float2 av0 = __half22float2(*(__half2*)&ts.y);   // Wl
        float2 a1  = __half22float2(*(__half2*)&ts.z);   // We feats 4li+2,4li+3
        float2 av1 = __half22float2(*(__half2*)&ts.w);
        float2 b0  = __half22float2(*(__half2*)&td.x);
        float2 bv0 = __half22float2(*(__half2*)&td.y);
        float2 b1  = __half22float2(*(__half2*)&td.z);
        float2 bv1 = __half22float2(*(__half2*)&td.w);

        float u0 = a0.x + b0.x + be1v.x;
        float u1 = a0.y + b0.y + be1v.y;
        float u2 = a1.x + b1.x + be1v.z;
        float u3 = a1.y + b1.y + be1v.w;
        float v0 = av0.x + bv0.x;
        float v1 = av0.y + bv0.y;
        float v2 = av1.x + bv1.x;
        float v3 = av1.y + bv1.y;
#pragma unroll
        for (int k = 0; k < 5; k++) {
            float ek = __shfl_sync(0xffffffffu, efl, base + k);
            u0 = fmaf(ek, we5[k].x, u0);
            u1 = fmaf(ek, we5[k].y, u1);
            u2 = fmaf(ek, we5[k].z, u2);
            u3 = fmaf(ek, we5[k].w, u3);
            v0 = fmaf(ek, wl5[k].x, v0);
            v1 = fmaf(ek, wl5[k].y, v1);
            v2 = fmaf(ek, wl5[k].z, v2);
            v3 = fmaf(ek, wl5[k].w, v3);
        }
        float part = tanh_fast(u0) * we2v.x + tanh_fast(u1) * we2v.y
                   + tanh_fast(u2) * we2v.z + tanh_fast(u3) * we2v.w;
#pragma unroll
        for (int o = 8; o > 0; o >>= 1) part += __shfl_xor_sync(0xffffffffu, part, o);
        float wgt = 1.f / (1.f + __expf(-(part + be2v)));
        float o0 = fmaxf(fmaf(wgt, v0, bl1v.x), 0.f);
        float o1 = fmaxf(fmaf(wgt, v1, bl1v.y), 0.f);
        float o2 = fmaxf(fmaf(wgt, v2, bl1v.z), 0.f);
        float o3 = fmaxf(fmaf(wgt, v3, bl1v.w), 0.f);
        float p2 = o0 * wl2v.x + o1 * wl2v.y + o2 * wl2v.z + o3 * wl2v.w;
#pragma unroll
        for (int o = 8; o > 0; o >>= 1) p2 += __shfl_xor_sync(0xffffffffu, p2, o);
        if (li == 0) out[e] = p2 + bl2v;
    }
}

// ---------------- launch -----------------------------------------------------
extern "C" void kernel_launch(void* const* d_in, const int* in_sizes, int n_in,
                              void* d_out, int out_size) {
    const float* node_feat = (const float*)d_in[0];
    const float* edge_feat = (const float*)d_in[1];
    const int*   src       = (const int*)d_in[2];
    const int*   dst       = (const int*)d_in[3];
    const float* W1s = (const float*)d_in[4];
    const float* W1n = (const float*)d_in[5];
    const float* b1  = (const float*)d_in[6];
    const float* W2s = (const float*)d_in[7];
    const float* W2n = (const float*)d_in[8];
    const float* b2  = (const float*)d_in[9];
    const float* Wnp = (const float*)d_in[10];
    const float* bnp = (const float*)d_in[11];
    const float* We1 = (const float*)d_in[12];
    const float* be1 = (const float*)d_in[13];
    const float* We2 = (const float*)d_in[14];
    const float* be2 = (const float*)d_in[15];
    const float* Wl1 = (const float*)d_in[16];
    const float* bl1 = (const float*)d_in[17];
    const float* Wl2 = (const float*)d_in[18];
    const float* bl2 = (const float*)d_in[19];
    float* out = (float*)d_out;

    float *ph1, *ph2;
    void *pst, *pdt, *pdeg, *pcnt;
    cudaGetSymbolAddress((void**)&ph1, g_h1);
    cudaGetSymbolAddress((void**)&ph2, g_h2);
    cudaGetSymbolAddress(&pst,  g_srct);
    cudaGetSymbolAddress(&pdt,  g_dstt);
    cudaGetSymbolAddress(&pdeg, g_deg);
    cudaGetSymbolAddress(&pcnt, g_cnt);

    int nb   = (NN + 1023) / 1024;
    int nblk = (NN + 7) / 8;          // warp-per-node kernels
    int g8   = (NN + 63) / 64;        // 8-node/warp GEMM kernels

    cudaMemsetAsync(pdeg, 0, NN * sizeof(int));
    cudaMemsetAsync(pcnt, 0, NN * sizeof(int));
    k_deg<<<(NE + 255) / 256, 256>>>(dst);
    k_scan1<<<nb, 1024>>>();
    k_scan2<<<1, 128>>>(nb);
    k_scan3<<<(NN + 255) / 256, 256>>>();
    k_scatter<<<(NE + 255) / 256, 256>>>(src, dst);

    // Layer 1
    k_proj1<<<(NN * 32 + 255) / 256, 256>>>(node_feat, W1n);
    k_sage1<<<nblk, 256>>>(node_feat, W1s, b1);

    // Layer 2: p2 = h1@W2n (half2) AND h1@W2s (fp32) in one fused pass
    k_gemm2s<<<g8, 256>>>(ph1, W2n, W2s, ph2);
    k_sage2b<<<nblk, 256>>>(b2);

    // hp = relu(h2@Wnp + bnp) into g_h1
    k_gemm8f<<<g8, 256>>>(ph2, Wnp, bnp, ph1);

    // per-node interleaved half2 tables
    k_tabk<<<g8, 256>>>(ph1, We1,           Wl1,           (uint2*)pst); // src-role rows 0..63
    k_tabk<<<g8, 256>>>(ph1, We1 + 64 * HD, Wl1 + 64 * HD, (uint2*)pdt); // dst-role rows 64..127

    // persistent fused edge stage: 16 lanes/edge, 2 edges/warp
    k_edge<<<1184, 256>>>(src, dst, edge_feat,
                          We1, be1, We2, be2, Wl1, bl1, Wl2, bl2, out);
}

// round 8
// speedup vs baseline: 1.1760x; 1.0286x over previous
#include <cuda_runtime.h>
#include <cuda_fp16.h>
#include <mma.h>

#define NN 100000
#define NE 1600000
#define HD 64

namespace wm = nvcuda::wmma;

// ---------------- scratch (device globals; no allocation allowed) ----------
__device__ int   g_deg[NN];
__device__ float g_inv[NN];
__device__ int   g_off[NN + 1];
__device__ int   g_bsum[128];
__device__ int   g_cnt[NN];
__device__ int   g_csr_src[NE];
__device__ __half2 g_p16[NN * 32];   // projected neighbor features (half2 pairs)
__device__ float g_h1[NN * HD];      // h1, later reused as hp
__device__ float g_h2[NN * HD];
// per-node tables, 16B-aligned: 16 x uint4 per node; as uint2[32]:
// idx j = {We-pair(feats 2j,2j+1) , Wl-pair} interleaved
__device__ uint4 g_srct[NN * 16];
__device__ uint4 g_dstt[NN * 16];

__device__ __forceinline__ float tanh_fast(float x) {
    float y;
    asm("tanh.approx.f32 %0, %1;" : "=f"(y) : "f"(x));
    return y;
}

// ---------------- degree histogram -----------------------------------------
__global__ void k_deg(const int* __restrict__ dst) {
    int e = blockIdx.x * blockDim.x + threadIdx.x;
    if (e < NE) atomicAdd(&g_deg[dst[e]], 1);
}

// ---------------- exclusive scan (3 kernels) --------------------------------
__global__ void k_scan1() {
    __shared__ int sh[1024];
    int tid = threadIdx.x;
    int i = blockIdx.x * 1024 + tid;
    int v = (i < NN) ? g_deg[i] : 0;
    sh[tid] = v;
    __syncthreads();
    for (int o = 1; o < 1024; o <<= 1) {
        int t = (tid >= o) ? sh[tid - o] : 0;
        __syncthreads();
        sh[tid] += t;
        __syncthreads();
    }
    if (i < NN) g_off[i] = sh[tid] - v;
    if (tid == 1023) g_bsum[blockIdx.x] = sh[1023];
}

__global__ void k_scan2(int nb) {
    __shared__ int sh[128];
    int tid = threadIdx.x;
    int v = (tid < nb) ? g_bsum[tid] : 0;
    sh[tid] = v;
    __syncthreads();
    for (int o = 1; o < 128; o <<= 1) {
        int t = (tid >= o) ? sh[tid - o] : 0;
        __syncthreads();
        sh[tid] += t;
        __syncthreads();
    }
    g_bsum[tid] = sh[tid] - v;
    if (tid == 127) g_off[NN] = sh[127];
}

__global__ void k_scan3() {
    int i = blockIdx.x * blockDim.x + threadIdx.x;
    if (i < NN) {
        g_off[i] += g_bsum[i >> 10];
        int d = g_deg[i];
        g_inv[i] = 1.0f / (float)(d > 0 ? d : 1);
    }
}

// ---------------- CSR scatter ------------------------------------------------
__global__ void k_scatter(const int* __restrict__ src, const int* __restrict__ dst) {
    int e = blockIdx.x * blockDim.x + threadIdx.x;
    if (e < NE) {
        int d = dst[e];
        int pos = atomicAdd(&g_cnt[d], 1);
        g_csr_src[g_off[d] + pos] = src[e];
    }
}

// ---------------- p1 = node_feat @ W1n  (4 x 64) -> half2 -------------------
__global__ void k_proj1(const float* __restrict__ nf, const float* __restrict__ W) {
    __shared__ float sW[4 * HD];
    int tid = threadIdx.x;
    sW[tid] = W[tid];
    __syncthreads();
    int idx = blockIdx.x * 256 + tid;
    if (idx >= NN * 32) return;
    int n = idx >> 5, j = idx & 31;
    const float* r = &nf[n * 4];
    float r0 = r[0], r1 = r[1], r2 = r[2], r3 = r[3];
    float v0 = r0 * sW[2*j]   + r1 * sW[64 + 2*j]   + r2 * sW[128 + 2*j]   + r3 * sW[192 + 2*j];
    float v1 = r0 * sW[2*j+1] + r1 * sW[64 + 2*j+1] + r2 * sW[128 + 2*j+1] + r3 * sW[192 + 2*j+1];
    g_p16[idx] = __floats2half2_rn(v0, v1);
}

// ---------------- SAGE layer 1 ----------------------------------------------
__global__ void k_sage1(const float* __restrict__ nf, const float* __restrict__ Ws,
                        const float* __restrict__ b) {
    __shared__ float sW[4 * HD];
    int tid = threadIdx.x;
    sW[tid] = Ws[tid];
    __syncthreads();
    int n = blockIdx.x * 8 + (tid >> 5);
    int l = tid & 31;
    if (n >= NN) return;
    int beg = g_off[n], end = g_off[n + 1];
    float ax = 0.f, ay = 0.f;
    int j = beg;
    for (; j + 4 <= end; j += 4) {
        int s0 = g_csr_src[j], s1 = g_csr_src[j + 1];
        int s2 = g_csr_src[j + 2], s3 = g_csr_src[j + 3];
        float2 q0 = __half22float2(g_p16[s0 * 32 + l]);
        float2 q1 = __half22float2(g_p16[s1 * 32 + l]);
        float2 q2 = __half22float2(g_p16[s2 * 32 + l]);
        float2 q3 = __half22float2(g_p16[s3 * 32 + l]);
        ax += (q0.x + q1.x) + (q2.x + q3.x);
        ay += (q0.y + q1.y) + (q2.y + q3.y);
    }
    for (; j < end; j++) {
        float2 q = __half22float2(g_p16[g_csr_src[j] * 32 + l]);
        ax += q.x; ay += q.y;
    }
    float iv = g_inv[n];
    const float* r = &nf[n * 4];
    float n0 = r[0], n1 = r[1], n2 = r[2], n3 = r[3];
    float sx = n0*sW[2*l]   + n1*sW[64+2*l]   + n2*sW[128+2*l]   + n3*sW[192+2*l];
    float sy = n0*sW[2*l+1] + n1*sW[64+2*l+1] + n2*sW[128+2*l+1] + n3*sW[192+2*l+1];
    float2 o;
    o.x = fmaxf(sx + ax * iv + b[2*l],     0.f);
    o.y = fmaxf(sy + ay * iv + b[2*l+1],   0.f);
    *(float2*)&g_h1[(size_t)n * HD + 2*l] = o;
}

// ================= WMMA GEMM stages (fp16 in, fp32 accum) ===================
// Common shape: X[128 nodes x 64] @ W[64 x 64]; 8 warps, warp w owns rows w*16..w*16+15.

// ---- dual: p16 = X@Wn (half2), outf = X@Ws (fp32), no bias ----------------
__global__ void k_wdual(const float* __restrict__ in, const float* __restrict__ Wn,
                        const float* __restrict__ Ws, float* __restrict__ outf) {
    __shared__ __align__(32) __half Xh[128 * HD];      // 16 KB
    __shared__ __align__(32) __half WA[HD * HD];       // 8 KB
    __shared__ __align__(32) __half WB[HD * HD];       // 8 KB
    __shared__ float scr[8][256];                      // 8 KB per-warp staging
    int tid = threadIdx.x, w = tid >> 5, lane = tid & 31;
    int nbase = blockIdx.x * 128;
    int base = nbase * HD;
    for (int t = tid; t < 128 * HD; t += 256) {
        int gi = base + t;
        Xh[t] = (gi < NN * HD) ? __float2half(in[gi]) : __half(0.f);
    }
    for (int t = tid; t < HD * HD; t += 256) {
        WA[t] = __float2half(Wn[t]);
        WB[t] = __float2half(Ws[t]);
    }
    __syncthreads();
    int r0 = w * 16;
#pragma unroll
    for (int nt = 0; nt < 4; nt++) {
        wm::fragment<wm::accumulator, 16, 16, 16, float> accA, accB;
        wm::fill_fragment(accA, 0.f);
        wm::fill_fragment(accB, 0.f);
#pragma unroll
        for (int kt = 0; kt < 4; kt++) {
            wm::fragment<wm::matrix_a, 16, 16, 16, __half, wm::row_major> a;
            wm::fragment<wm::matrix_b, 16, 16, 16, __half, wm::row_major> bA, bB;
            wm::load_matrix_sync(a, Xh + r0 * HD + kt * 16, HD);
            wm::load_matrix_sync(bA, WA + kt * 16 * HD + nt * 16, HD);
            wm::load_matrix_sync(bB, WB + kt * 16 * HD + nt * 16, HD);
            wm::mma_sync(accA, a, bA, accA);
            wm::mma_sync(accB, a, bB, accB);
        }
        // fp32 out (Ws path)
        wm::store_matrix_sync(scr[w], accB, 16, wm::mem_row_major);
        __syncwarp();
        for (int t = lane; t < 256; t += 32) {
            int row = t >> 4, col = t & 15;
            int n = nbase + r0 + row;
            if (n < NN) outf[(size_t)n * HD + nt * 16 + col] = scr[w][t];
        }
        __syncwarp();
        // half2 out (Wn path -> g_p16)
        wm::store_matrix_sync(scr[w], accA, 16, wm::mem_row_major);
        __syncwarp();
        for (int t = lane; t < 128; t += 32) {
            int row = t >> 3, cp = t & 7;
            int n = nbase + r0 + row;
            if (n < NN)
                g_p16[(size_t)n * 32 + nt * 8 + cp] =
                    __floats2half2_rn(scr[w][row * 16 + 2 * cp], scr[w][row * 16 + 2 * cp + 1]);
        }
        __syncwarp();
    }
}

// ---- single: out = relu(X@W + bias) ----------------------------------------
__global__ void k_wbias(const float* __restrict__ in, const float* __restrict__ W,
                        const float* __restrict__ bias, float* __restrict__ out) {
    __shared__ __align__(32) __half Xh[128 * HD];
    __shared__ __align__(32) __half WA[HD * HD];
    __shared__ float scr[8][256];
    __shared__ float sb[HD];
    int tid = threadIdx.x, w = tid >> 5, lane = tid & 31;
    int nbase = blockIdx.x * 128;
    int base = nbase * HD;
    for (int t = tid; t < 128 * HD; t += 256) {
        int gi = base + t;
        Xh[t] = (gi < NN * HD) ? __float2half(in[gi]) : __half(0.f);
    }
    for (int t = tid; t < HD * HD; t += 256) WA[t] = __float2half(W[t]);
    if (tid < HD) sb[tid] = bias[tid];
    __syncthreads();
    int r0 = w * 16;
#pragma unroll
    for (int nt = 0; nt < 4; nt++) {
        wm::fragment<wm::accumulator, 16, 16, 16, float> acc;
        wm::fill_fragment(acc, 0.f);
#pragma unroll
        for (int kt = 0; kt < 4; kt++) {
            wm::fragment<wm::matrix_a, 16, 16, 16, __half, wm::row_major> a;
            wm::fragment<wm::matrix_b, 16, 16, 16, __half, wm::row_major> b;
            wm::load_matrix_sync(a, Xh + r0 * HD + kt * 16, HD);
            wm::load_matrix_sync(b, WA + kt * 16 * HD + nt * 16, HD);
            wm::mma_sync(acc, a, b, acc);
        }
        wm::store_matrix_sync(scr[w], acc, 16, wm::mem_row_major);
        __syncwarp();
        for (int t = lane; t < 256; t += 32) {
            int row = t >> 4, col = t & 15;
            int n = nbase + r0 + row;
            if (n < NN)
                out[(size_t)n * HD + nt * 16 + col] = fmaxf(scr[w][t] + sb[nt * 16 + col], 0.f);
        }
        __syncwarp();
    }
}

// ---- tables: dual GEMM, interleaved half2 output (split uint stores) -------
__global__ void k_wtab(const float* __restrict__ hp, const float* __restrict__ Wa,
                       const float* __restrict__ Wb, unsigned int* __restrict__ utab) {
    __shared__ __align__(32) __half Xh[128 * HD];      // 16 KB
    __shared__ __align__(32) __half WA[HD * HD];       // 8 KB (We part)
    __shared__ __align__(32) __half WB[HD * HD];       // 8 KB (Wl part)
    __shared__ float scr[8][256];                      // 8 KB
    int tid = threadIdx.x, w = tid >> 5, lane = tid & 31;
    int nbase = blockIdx.x * 128;
    int base = nbase * HD;
    for (int t = tid; t < 128 * HD; t += 256) {
        int gi = base + t;
        Xh[t] = (gi < NN * HD) ? __float2half(hp[gi]) : __half(0.f);
    }
    for (int t = tid; t < HD * HD; t += 256) {
        WA[t] = __float2half(Wa[t]);
        WB[t] = __float2half(Wb[t]);
    }
    __syncthreads();
    int r0 = w * 16;
#pragma unroll
    for (int nt = 0; nt < 4; nt++) {
        wm::fragment<wm::accumulator, 16, 16, 16, float> accA, accB;
        wm::fill_fragment(accA, 0.f);
        wm::fill_fragment(accB, 0.f);
#pragma unroll
        for (int kt = 0; kt < 4; kt++) {
            wm::fragment<wm::matrix_a, 16, 16, 16, __half, wm::row_major> a;
            wm::fragment<wm::matrix_b, 16, 16, 16, __half, wm::row_major> bA, bB;
            wm::load_matrix_sync(a, Xh + r0 * HD + kt * 16, HD);
            wm::load_matrix_sync(bA, WA + kt * 16 * HD + nt * 16, HD);
            wm::load_matrix_sync(bB, WB + kt * 16 * HD + nt * 16, HD);
            wm::mma_sync(accA, a, bA, accA);
            wm::mma_sync(accB, a, bB, accB);
        }
        // We part -> x slot of uint2 pair  (utab index = (n*32 + j)*2)
        wm::store_matrix_sync(scr[w], accA, 16, wm::mem_row_major);
        __syncwarp();
        for (int t = lane; t < 128; t += 32) {
            int row = t >> 3, cp = t & 7;
            int n = nbase + r0 + row;
            if (n < NN) {
                __half2 h = __floats2half2_rn(scr[w][row * 16 + 2 * cp], scr[w][row * 16 + 2 * cp + 1]);
                utab[((size_t)n * 32 + nt * 8 + cp) * 2] = *(unsigned int*)&h;
            }
        }
        __syncwarp();
        // Wl part -> y slot
        wm::store_matrix_sync(scr[w], accB, 16, wm::mem_row_major);
        __syncwarp();
        for (int t = lane; t < 128; t += 32) {
            int row = t >> 3, cp = t & 7;
            int n = nbase + r0 + row;
            if (n < NN) {
                __half2 h = __floats2half2_rn(scr[w][row * 16 + 2 * cp], scr[w][row * 16 + 2 * cp + 1]);
                utab[((size_t)n * 32 + nt * 8 + cp) * 2 + 1] = *(unsigned int*)&h;
            }
        }
        __syncwarp();
    }
}

// ---------------- SAGE layer 2 combine: h2 = relu(h2 + agg*inv + b2) --------
__global__ void k_sage2b(const float* __restrict__ b) {
    int tid = threadIdx.x;
    int n = blockIdx.x * 8 + (tid >> 5);
    int l = tid & 31;
    if (n >= NN) return;
    int beg = g_off[n], end = g_off[n + 1];
    float ax = 0.f, ay = 0.f;
    int j = beg;
    for (; j + 4 <= end; j += 4) {
        int s0 = g_csr_src[j], s1 = g_csr_src[j + 1];
        int s2 = g_csr_src[j + 2], s3 = g_csr_src[j + 3];
        float2 q0 = __half22float2(g_p16[s0 * 32 + l]);
        float2 q1 = __half22float2(g_p16[s1 * 32 + l]);
        float2 q2 = __half22float2(g_p16[s2 * 32 + l]);
        float2 q3 = __half22float2(g_p16[s3 * 32 + l]);
        ax += (q0.x + q1.x) + (q2.x + q3.x);
        ay += (q0.y + q1.y) + (q2.y + q3.y);
    }
    for (; j < end; j++) {
        float2 q = __half22float2(g_p16[g_csr_src[j] * 32 + l]);
        ax += q.x; ay += q.y;
    }
    float iv = g_inv[n];
    float2 t = *(const float2*)&g_h2[(size_t)n * HD + 2 * l];
    float2 o;
    o.x = fmaxf(t.x + ax * iv + b[2 * l],     0.f);
    o.y = fmaxf(t.y + ay * iv + b[2 * l + 1], 0.f);
    *(float2*)&g_h2[(size_t)n * HD + 2 * l] = o;
}

// ------- edge kernel: 16 lanes/edge, 2 edges/warp, persistent ----------------
__global__ void k_edge(const int* __restrict__ src, const int* __restrict__ dst,
                       const float* __restrict__ ef,
                       const float* __restrict__ We1, const float* __restrict__ be1,
                       const float* __restrict__ We2, const float* __restrict__ be2,
                       const float* __restrict__ Wl1, const float* __restrict__ bl1,
                       const float* __restrict__ Wl2, const float* __restrict__ bl2,
                       float* __restrict__ out) {
    int tid = threadIdx.x;
    int l = tid & 31;
    int li = l & 15;            // lane within 16-lane edge group
    int g = l >> 4;             // which of the 2 edges
    int base = l & 16;          // shfl base for my group
    int warp = (blockIdx.x * blockDim.x + tid) >> 5;
    int nw = (gridDim.x * blockDim.x) >> 5;

    float4 we5[5], wl5[5];
#pragma unroll
    for (int k = 0; k < 5; k++) {
        we5[k] = *(const float4*)&We1[(128 + k) * HD + 4 * li];
        wl5[k] = *(const float4*)&Wl1[(128 + k) * HD + 4 * li];
    }
    float4 be1v = *(const float4*)&be1[4 * li];
    float4 bl1v = *(const float4*)&bl1[4 * li];
    float4 we2v = *(const float4*)&We2[4 * li];
    float4 wl2v = *(const float4*)&Wl2[4 * li];
    float be2v = be2[0], bl2v = bl2[0];

    for (int eb = warp * 2; eb < NE; eb += 2 * nw) {
        int e = eb + g;
        int s = __ldg(&src[e]);
        int d = __ldg(&dst[e]);
        uint4 ts = *(const uint4*)((const uint2*)&g_srct[(size_t)s * 16] + 2 * li);
        uint4 td = *(const uint4*)((const uint2*)&g_dstt[(size_t)d * 16] + 2 * li);
        float efl = (li < 5) ? __ldg(&ef[(size_t)e * 5 + li]) : 0.f;

        float2 a0  = __half22float2(*(__half2*)&ts.x);
        float2 av0 = __half22float2(*(__half2*)&ts.y);
        float2 a1  = __half22float2(*(__half2*)&ts.z);
        float2 av1 = __half22float2(*(__half2*)&ts.w);
        float2 b0  = __half22float2(*(__half2*)&td.x);
        float2 bv0 = __half22float2(*(__half2*)&td.y);
        float2 b1  = __half22float2(*(__half2*)&td.z);
        float2 bv1 = __half22float2(*(__half2*)&td.w);

        float u0 = a0.x + b0.x + be1v.x;
        float u1 = a0.y + b0.y + be1v.y;
        float u2 = a1.x + b1.x + be1v.z;
        float u3 = a1.y + b1.y + be1v.w;
        float v0 = av0.x + bv0.x;
        float v1 = av0.y + bv0.y;
        float v2 = av1.x + bv1.x;
        float v3 = av1.y + bv1.y;
#pragma unroll
        for (int k = 0; k < 5; k++) {
            float ek = __shfl_sync(0xffffffffu, efl, base + k);
            u0 = fmaf(ek, we5[k].x, u0);
            u1 = fmaf(ek, we5[k].y, u1);
            u2 = fmaf(ek, we5[k].z, u2);
            u3 = fmaf(ek, we5[k].w, u3);
            v0 = fmaf(ek, wl5[k].x, v0);
            v1 = fmaf(ek, wl5[k].y, v1);
            v2 = fmaf(ek, wl5[k].z, v2);
            v3 = fmaf(ek, wl5[k].w, v3);
        }
        float part = tanh_fast(u0) * we2v.x + tanh_fast(u1) * we2v.y
                   + tanh_fast(u2) * we2v.z + tanh_fast(u3) * we2v.w;
#pragma unroll
        for (int o = 8; o > 0; o >>= 1) part += __shfl_xor_sync(0xffffffffu, part, o);
        float wgt = 1.f / (1.f + __expf(-(part + be2v)));
        float o0 = fmaxf(fmaf(wgt, v0, bl1v.x), 0.f);
        float o1 = fmaxf(fmaf(wgt, v1, bl1v.y), 0.f);
        float o2 = fmaxf(fmaf(wgt, v2, bl1v.z), 0.f);
        float o3 = fmaxf(fmaf(wgt, v3, bl1v.w), 0.f);
        float p2 = o0 * wl2v.x + o1 * wl2v.y + o2 * wl2v.z + o3 * wl2v.w;
#pragma unroll
        for (int o = 8; o > 0; o >>= 1) p2 += __shfl_xor_sync(0xffffffffu, p2, o);
        if (li == 0) out[e] = p2 + bl2v;
    }
}

// ---------------- launch -----------------------------------------------------
extern "C" void kernel_launch(void* const* d_in, const int* in_sizes, int n_in,
                              void* d_out, int out_size) {
    const float* node_feat = (const float*)d_in[0];
    const float* edge_feat = (const float*)d_in[1];
    const int*   src       = (const int*)d_in[2];
    const int*   dst       = (const int*)d_in[3];
    const float* W1s = (const float*)d_in[4];
    const float* W1n = (const float*)d_in[5];
    const float* b1  = (const float*)d_in[6];
    const float* W2s = (const float*)d_in[7];
    const float* W2n = (const float*)d_in[8];
    const float* b2  = (const float*)d_in[9];
    const float* Wnp = (const float*)d_in[10];
    const float* bnp = (const float*)d_in[11];
    const float* We1 = (const float*)d_in[12];
    const float* be1 = (const float*)d_in[13];
    const float* We2 = (const float*)d_in[14];
    const float* be2 = (const float*)d_in[15];
    const float* Wl1 = (const float*)d_in[16];
    const float* bl1 = (const float*)d_in[17];
    const float* Wl2 = (const float*)d_in[18];
    const float* bl2 = (const float*)d_in[19];
    float* out = (float*)d_out;

    float *ph1, *ph2;
    void *pst, *pdt, *pdeg, *pcnt;
    cudaGetSymbolAddress((void**)&ph1, g_h1);
    cudaGetSymbolAddress((void**)&ph2, g_h2);
    cudaGetSymbolAddress(&pst,  g_srct);
    cudaGetSymbolAddress(&pdt,  g_dstt);
    cudaGetSymbolAddress(&pdeg, g_deg);
    cudaGetSymbolAddress(&pcnt, g_cnt);

    int nb   = (NN + 1023) / 1024;
    int nblk = (NN + 7) / 8;          // warp-per-node kernels
    int wblk = (NN + 127) / 128;      // WMMA kernels (128 nodes/block)

    cudaMemsetAsync(pdeg, 0, NN * sizeof(int));
    cudaMemsetAsync(pcnt, 0, NN * sizeof(int));
    k_deg<<<(NE + 255) / 256, 256>>>(dst);
    k_scan1<<<nb, 1024>>>();
    k_scan2<<<1, 128>>>(nb);
    k_scan3<<<(NN + 255) / 256, 256>>>();
    k_scatter<<<(NE + 255) / 256, 256>>>(src, dst);

    // Layer 1
    k_proj1<<<(NN * 32 + 255) / 256, 256>>>(node_feat, W1n);
    k_sage1<<<nblk, 256>>>(node_feat, W1s, b1);

    // Layer 2: p2 = h1@W2n (half2) AND h1@W2s (fp32) via WMMA, then combine
    k_wdual<<<wblk, 256>>>(ph1, W2n, W2s, ph2);
    k_sage2b<<<nblk, 256>>>(b2);

    // hp = relu(h2@Wnp + bnp) into g_h1 (WMMA)
    k_wbias<<<wblk, 256>>>(ph2, Wnp, bnp, ph1);

    // per-node interleaved half2 tables (WMMA dual)
    k_wtab<<<wblk, 256>>>(ph1, We1,           Wl1,           (unsigned int*)pst);
    k_wtab<<<wblk, 256>>>(ph1, We1 + 64 * HD, Wl1 + 64 * HD, (unsigned int*)pdt);

    // persistent fused edge stage: 16 lanes/edge, 2 edges/warp
    k_edge<<<1184, 256>>>(src, dst, edge_feat,
                          We1, be1, We2, be2, Wl1, bl1, Wl2, bl2, out);
}

// round 9
// speedup vs baseline: 1.5719x; 1.3367x over previous
#include <cuda_runtime.h>
#include <cuda_fp16.h>
#include <mma.h>

#define NN 100000
#define NE 1600000
#define HD 64

namespace wm = nvcuda::wmma;

// ---------------- scratch (device globals; no allocation allowed) ----------
__device__ int   g_deg[NN];
__device__ float g_inv[NN];
__device__ int   g_off[NN + 1];
__device__ int   g_bsum[128];
__device__ int   g_cnt[NN];
__device__ int   g_csr_src[NE];
__device__ __half2 g_p16[NN * 32];   // projected neighbor features (half2 pairs)
__device__ float g_h1[NN * HD];      // h1, later reused as hp
__device__ float g_h2[NN * HD];
// per-node tables, 16B-aligned: 16 x uint4 per node; as uint2[32]:
// idx j = {We-pair(feats 2j,2j+1) , Wl-pair} interleaved
__device__ uint4 g_srct[NN * 16];
__device__ uint4 g_dstt[NN * 16];

__device__ __forceinline__ float tanh_fast(float x) {
    float y;
    asm("tanh.approx.f32 %0, %1;" : "=f"(y) : "f"(x));
    return y;
}

// ---------------- degree histogram -----------------------------------------
__global__ void k_deg(const int* __restrict__ dst) {
    int e = blockIdx.x * blockDim.x + threadIdx.x;
    if (e < NE) atomicAdd(&g_deg[dst[e]], 1);
}

// ---------------- exclusive scan (3 kernels) --------------------------------
__global__ void k_scan1() {
    __shared__ int sh[1024];
    int tid = threadIdx.x;
    int i = blockIdx.x * 1024 + tid;
    int v = (i < NN) ? g_deg[i] : 0;
    sh[tid] = v;
    __syncthreads();
    for (int o = 1; o < 1024; o <<= 1) {
        int t = (tid >= o) ? sh[tid - o] : 0;
        __syncthreads();
        sh[tid] += t;
        __syncthreads();
    }
    if (i < NN) g_off[i] = sh[tid] - v;
    if (tid == 1023) g_bsum[blockIdx.x] = sh[1023];
}

__global__ void k_scan2(int nb) {
    __shared__ int sh[128];
    int tid = threadIdx.x;
    int v = (tid < nb) ? g_bsum[tid] : 0;
    sh[tid] = v;
    __syncthreads();
    for (int o = 1; o < 128; o <<= 1) {
        int t = (tid >= o) ? sh[tid - o] : 0;
        __syncthreads();
        sh[tid] += t;
        __syncthreads();
    }
    g_bsum[tid] = sh[tid] - v;
    if (tid == 127) g_off[NN] = sh[127];
}

__global__ void k_scan3() {
    int i = blockIdx.x * blockDim.x + threadIdx.x;
    if (i < NN) {
        g_off[i] += g_bsum[i >> 10];
        int d = g_deg[i];
        g_inv[i] = 1.0f / (float)(d > 0 ? d : 1);
    }
}

// ---------------- CSR scatter ------------------------------------------------
__global__ void k_scatter(const int* __restrict__ src, const int* __restrict__ dst) {
    int e = blockIdx.x * blockDim.x + threadIdx.x;
    if (e < NE) {
        int d = dst[e];
        int pos = atomicAdd(&g_cnt[d], 1);
        g_csr_src[g_off[d] + pos] = src[e];
    }
}

// ---------------- p1 = node_feat @ W1n  (4 x 64) -> half2 -------------------
__global__ void k_proj1(const float* __restrict__ nf, const float* __restrict__ W) {
    __shared__ float sW[4 * HD];
    int tid = threadIdx.x;
    sW[tid] = W[tid];
    __syncthreads();
    int idx = blockIdx.x * 256 + tid;
    if (idx >= NN * 32) return;
    int n = idx >> 5, j = idx & 31;
    const float* r = &nf[n * 4];
    float r0 = r[0], r1 = r[1], r2 = r[2], r3 = r[3];
    float v0 = r0 * sW[2*j]   + r1 * sW[64 + 2*j]   + r2 * sW[128 + 2*j]   + r3 * sW[192 + 2*j];
    float v1 = r0 * sW[2*j+1] + r1 * sW[64 + 2*j+1] + r2 * sW[128 + 2*j+1] + r3 * sW[192 + 2*j+1];
    g_p16[idx] = __floats2half2_rn(v0, v1);
}

// ---------------- SAGE layer 1 ----------------------------------------------
__global__ void k_sage1(const float* __restrict__ nf, const float* __restrict__ Ws,
                        const float* __restrict__ b) {
    __shared__ float sW[4 * HD];
    int tid = threadIdx.x;
    sW[tid] = Ws[tid];
    __syncthreads();
    int n = blockIdx.x * 8 + (tid >> 5);
    int l = tid & 31;
    if (n >= NN) return;
    int beg = g_off[n], end = g_off[n + 1];
    float ax = 0.f, ay = 0.f;
    int j = beg;
    for (; j + 4 <= end; j += 4) {
        int s0 = g_csr_src[j], s1 = g_csr_src[j + 1];
        int s2 = g_csr_src[j + 2], s3 = g_csr_src[j + 3];
        float2 q0 = __half22float2(g_p16[s0 * 32 + l]);
        float2 q1 = __half22float2(g_p16[s1 * 32 + l]);
        float2 q2 = __half22float2(g_p16[s2 * 32 + l]);
        float2 q3 = __half22float2(g_p16[s3 * 32 + l]);
        ax += (q0.x + q1.x) + (q2.x + q3.x);
        ay += (q0.y + q1.y) + (q2.y + q3.y);
    }
    for (; j < end; j++) {
        float2 q = __half22float2(g_p16[g_csr_src[j] * 32 + l]);
        ax += q.x; ay += q.y;
    }
    float iv = g_inv[n];
    const float* r = &nf[n * 4];
    float n0 = r[0], n1 = r[1], n2 = r[2], n3 = r[3];
    float sx = n0*sW[2*l]   + n1*sW[64+2*l]   + n2*sW[128+2*l]   + n3*sW[192+2*l];
    float sy = n0*sW[2*l+1] + n1*sW[64+2*l+1] + n2*sW[128+2*l+1] + n3*sW[192+2*l+1];
    float2 o;
    o.x = fmaxf(sx + ax * iv + b[2*l],     0.f);
    o.y = fmaxf(sy + ay * iv + b[2*l+1],   0.f);
    *(float2*)&g_h1[(size_t)n * HD + 2*l] = o;
}

// ================= WMMA GEMM stages (fp16 in, fp32 accum) ===================

// ---- dual: p16 = X@Wn (half2), outf = X@Ws (fp32), no bias ----------------
__global__ void k_wdual(const float* __restrict__ in, const float* __restrict__ Wn,
                        const float* __restrict__ Ws, float* __restrict__ outf) {
    __shared__ __align__(32) __half Xh[128 * HD];
    __shared__ __align__(32) __half WA[HD * HD];
    __shared__ __align__(32) __half WB[HD * HD];
    __shared__ float scr[8][256];
    int tid = threadIdx.x, w = tid >> 5, lane = tid & 31;
    int nbase = blockIdx.x * 128;
    int base = nbase * HD;
    for (int t = tid; t < 128 * HD; t += 256) {
        int gi = base + t;
        Xh[t] = (gi < NN * HD) ? __float2half(in[gi]) : __half(0.f);
    }
    for (int t = tid; t < HD * HD; t += 256) {
        WA[t] = __float2half(Wn[t]);
        WB[t] = __float2half(Ws[t]);
    }
    __syncthreads();
    int r0 = w * 16;
#pragma unroll
    for (int nt = 0; nt < 4; nt++) {
        wm::fragment<wm::accumulator, 16, 16, 16, float> accA, accB;
        wm::fill_fragment(accA, 0.f);
        wm::fill_fragment(accB, 0.f);
#pragma unroll
        for (int kt = 0; kt < 4; kt++) {
            wm::fragment<wm::matrix_a, 16, 16, 16, __half, wm::row_major> a;
            wm::fragment<wm::matrix_b, 16, 16, 16, __half, wm::row_major> bA, bB;
            wm::load_matrix_sync(a, Xh + r0 * HD + kt * 16, HD);
            wm::load_matrix_sync(bA, WA + kt * 16 * HD + nt * 16, HD);
            wm::load_matrix_sync(bB, WB + kt * 16 * HD + nt * 16, HD);
            wm::mma_sync(accA, a, bA, accA);
            wm::mma_sync(accB, a, bB, accB);
        }
        wm::store_matrix_sync(scr[w], accB, 16, wm::mem_row_major);
        __syncwarp();
        for (int t = lane; t < 256; t += 32) {
            int row = t >> 4, col = t & 15;
            int n = nbase + r0 + row;
            if (n < NN) outf[(size_t)n * HD + nt * 16 + col] = scr[w][t];
        }
        __syncwarp();
        wm::store_matrix_sync(scr[w], accA, 16, wm::mem_row_major);
        __syncwarp();
        for (int t = lane; t < 128; t += 32) {
            int row = t >> 3, cp = t & 7;
            int n = nbase + r0 + row;
            if (n < NN)
                g_p16[(size_t)n * 32 + nt * 8 + cp] =
                    __floats2half2_rn(scr[w][row * 16 + 2 * cp], scr[w][row * 16 + 2 * cp + 1]);
        }
        __syncwarp();
    }
}

// ---- single: out = relu(X@W + bias) ----------------------------------------
__global__ void k_wbias(const float* __restrict__ in, const float* __restrict__ W,
                        const float* __restrict__ bias, float* __restrict__ out) {
    __shared__ __align__(32) __half Xh[128 * HD];
    __shared__ __align__(32) __half WA[HD * HD];
    __shared__ float scr[8][256];
    __shared__ float sb[HD];
    int tid = threadIdx.x, w = tid >> 5, lane = tid & 31;
    int nbase = blockIdx.x * 128;
    int base = nbase * HD;
    for (int t = tid; t < 128 * HD; t += 256) {
        int gi = base + t;
        Xh[t] = (gi < NN * HD) ? __float2half(in[gi]) : __half(0.f);
    }
    for (int t = tid; t < HD * HD; t += 256) WA[t] = __float2half(W[t]);
    if (tid < HD) sb[tid] = bias[tid];
    __syncthreads();
    int r0 = w * 16;
#pragma unroll
    for (int nt = 0; nt < 4; nt++) {
        wm::fragment<wm::accumulator, 16, 16, 16, float> acc;
        wm::fill_fragment(acc, 0.f);
#pragma unroll
        for (int kt = 0; kt < 4; kt++) {
            wm::fragment<wm::matrix_a, 16, 16, 16, __half, wm::row_major> a;
            wm::fragment<wm::matrix_b, 16, 16, 16, __half, wm::row_major> b;
            wm::load_matrix_sync(a, Xh + r0 * HD + kt * 16, HD);
            wm::load_matrix_sync(b, WA + kt * 16 * HD + nt * 16, HD);
            wm::mma_sync(acc, a, b, acc);
        }
        wm::store_matrix_sync(scr[w], acc, 16, wm::mem_row_major);
        __syncwarp();
        for (int t = lane; t < 256; t += 32) {
            int row = t >> 4, col = t & 15;
            int n = nbase + r0 + row;
            if (n < NN)
                out[(size_t)n * HD + nt * 16 + col] = fmaxf(scr[w][t] + sb[nt * 16 + col], 0.f);
        }
        __syncwarp();
    }
}

// ---- tables: dual GEMM, both roles via blockIdx.y --------------------------
__global__ void k_wtab(const float* __restrict__ hp, const float* __restrict__ We1,
                       const float* __restrict__ Wl1,
                       unsigned int* __restrict__ utab_s, unsigned int* __restrict__ utab_d) {
    __shared__ __align__(32) __half Xh[128 * HD];
    __shared__ __align__(32) __half WA[HD * HD];
    __shared__ __align__(32) __half WB[HD * HD];
    __shared__ float scr[8][256];
    int tid = threadIdx.x, w = tid >> 5, lane = tid & 31;
    int role = blockIdx.y;
    const float* Wa = We1 + role * 64 * HD;
    const float* Wb = Wl1 + role * 64 * HD;
    unsigned int* utab = role ? utab_d : utab_s;
    int nbase = blockIdx.x * 128;
    int base = nbase * HD;
    for (int t = tid; t < 128 * HD; t += 256) {
        int gi = base + t;
        Xh[t] = (gi < NN * HD) ? __float2half(hp[gi]) : __half(0.f);
    }
    for (int t = tid; t < HD * HD; t += 256) {
        WA[t] = __float2half(Wa[t]);
        WB[t] = __float2half(Wb[t]);
    }
    __syncthreads();
    int r0 = w * 16;
#pragma unroll
    for (int nt = 0; nt < 4; nt++) {
        wm::fragment<wm::accumulator, 16, 16, 16, float> accA, accB;
        wm::fill_fragment(accA, 0.f);
        wm::fill_fragment(accB, 0.f);
#pragma unroll
        for (int kt = 0; kt < 4; kt++) {
            wm::fragment<wm::matrix_a, 16, 16, 16, __half, wm::row_major> a;
            wm::fragment<wm::matrix_b, 16, 16, 16, __half, wm::row_major> bA, bB;
            wm::load_matrix_sync(a, Xh + r0 * HD + kt * 16, HD);
            wm::load_matrix_sync(bA, WA + kt * 16 * HD + nt * 16, HD);
            wm::load_matrix_sync(bB, WB + kt * 16 * HD + nt * 16, HD);
            wm::mma_sync(accA, a, bA, accA);
            wm::mma_sync(accB, a, bB, accB);
        }
        wm::store_matrix_sync(scr[w], accA, 16, wm::mem_row_major);
        __syncwarp();
        for (int t = lane; t < 128; t += 32) {
            int row = t >> 3, cp = t & 7;
            int n = nbase + r0 + row;
            if (n < NN) {
                __half2 h = __floats2half2_rn(scr[w][row * 16 + 2 * cp], scr[w][row * 16 + 2 * cp + 1]);
                utab[((size_t)n * 32 + nt * 8 + cp) * 2] = *(unsigned int*)&h;
            }
        }
        __syncwarp();
        wm::store_matrix_sync(scr[w], accB, 16, wm::mem_row_major);
        __syncwarp();
        for (int t = lane; t < 128; t += 32) {
            int row = t >> 3, cp = t & 7;
            int n = nbase + r0 + row;
            if (n < NN) {
                __half2 h = __floats2half2_rn(scr[w][row * 16 + 2 * cp], scr[w][row * 16 + 2 * cp + 1]);
                utab[((size_t)n * 32 + nt * 8 + cp) * 2 + 1] = *(unsigned int*)&h;
            }
        }
        __syncwarp();
    }
}

// ---------------- SAGE layer 2 combine: h2 = relu(h2 + agg*inv + b2) --------
__global__ void k_sage2b(const float* __restrict__ b) {
    int tid = threadIdx.x;
    int n = blockIdx.x * 8 + (tid >> 5);
    int l = tid & 31;
    if (n >= NN) return;
    int beg = g_off[n], end = g_off[n + 1];
    float ax = 0.f, ay = 0.f;
    int j = beg;
    for (; j + 4 <= end; j += 4) {
        int s0 = g_csr_src[j], s1 = g_csr_src[j + 1];
        int s2 = g_csr_src[j + 2], s3 = g_csr_src[j + 3];
        float2 q0 = __half22float2(g_p16[s0 * 32 + l]);
        float2 q1 = __half22float2(g_p16[s1 * 32 + l]);
        float2 q2 = __half22float2(g_p16[s2 * 32 + l]);
        float2 q3 = __half22float2(g_p16[s3 * 32 + l]);
        ax += (q0.x + q1.x) + (q2.x + q3.x);
        ay += (q0.y + q1.y) + (q2.y + q3.y);
    }
    for (; j < end; j++) {
        float2 q = __half22float2(g_p16[g_csr_src[j] * 32 + l]);
        ax += q.x; ay += q.y;
    }
    float iv = g_inv[n];
    float2 t = *(const float2*)&g_h2[(size_t)n * HD + 2 * l];
    float2 o;
    o.x = fmaxf(t.x + ax * iv + b[2 * l],     0.f);
    o.y = fmaxf(t.y + ay * iv + b[2 * l + 1], 0.f);
    *(float2*)&g_h2[(size_t)n * HD + 2 * l] = o;
}

// ------- edge kernel: 16 lanes/edge, 2 edges/warp, half2 math ----------------
__global__ void k_edge(const int* __restrict__ src, const int* __restrict__ dst,
                       const float* __restrict__ ef,
                       const float* __restrict__ We1, const float* __restrict__ be1,
                       const float* __restrict__ We2, const float* __restrict__ be2,
                       const float* __restrict__ Wl1, const float* __restrict__ bl1,
                       const float* __restrict__ Wl2, const float* __restrict__ bl2,
                       float* __restrict__ out) {
    int tid = threadIdx.x;
    int l = tid & 31;
    int li = l & 15;            // lane within 16-lane edge group
    int g = l >> 4;             // which of the 2 edges
    int base = l & 16;          // shfl base for my group
    int warp = (blockIdx.x * blockDim.x + tid) >> 5;
    int nw = (gridDim.x * blockDim.x) >> 5;

    // per-lane constants, packed half2 where used in the hot loop
    __half2 wehA[5], wehB[5], wlhA[5], wlhB[5];
#pragma unroll
    for (int k = 0; k < 5; k++) {
        float4 we = *(const float4*)&We1[(128 + k) * HD + 4 * li];
        float4 wl = *(const float4*)&Wl1[(128 + k) * HD + 4 * li];
        wehA[k] = __floats2half2_rn(we.x, we.y);
        wehB[k] = __floats2half2_rn(we.z, we.w);
        wlhA[k] = __floats2half2_rn(wl.x, wl.y);
        wlhB[k] = __floats2half2_rn(wl.z, wl.w);
    }
    float4 be1f = *(const float4*)&be1[4 * li];
    __half2 be1hA = __floats2half2_rn(be1f.x, be1f.y);
    __half2 be1hB = __floats2half2_rn(be1f.z, be1f.w);
    float4 bl1v = *(const float4*)&bl1[4 * li];
    float4 we2v = *(const float4*)&We2[4 * li];
    float4 wl2v = *(const float4*)&Wl2[4 * li];
    float be2v = be2[0], bl2v = bl2[0];

    int e = warp * 2 + g;
    int s = 0, d = 0;
    float efl = 0.f;
    if (e < NE) {
        s = __ldg(&src[e]);
        d = __ldg(&dst[e]);
        efl = (li < 5) ? __ldg(&ef[(size_t)e * 5 + li]) : 0.f;
    }
    for (int eb = warp * 2; eb < NE; eb += 2 * nw) {
        // gathers for current edge issue immediately (s,d prefetched)
        uint4 ts = *(const uint4*)((const uint2*)&g_srct[(size_t)s * 16] + 2 * li);
        uint4 td = *(const uint4*)((const uint2*)&g_dstt[(size_t)d * 16] + 2 * li);
        __half2 efh = __float2half2_rn(efl);
        int ecur = eb + g;

        // prefetch next iteration's indices/features
        int enext = eb + 2 * nw + g;
        if (enext < NE) {
            s = __ldg(&src[enext]);
            d = __ldg(&dst[enext]);
            efl = (li < 5) ? __ldg(&ef[(size_t)enext * 5 + li]) : 0.f;
        }

        __half2 uA = __hadd2(__hadd2(*(__half2*)&ts.x, *(__half2*)&td.x), be1hA);
        __half2 uB = __hadd2(__hadd2(*(__half2*)&ts.z, *(__half2*)&td.z), be1hB);
        __half2 vA = __hadd2(*(__half2*)&ts.y, *(__half2*)&td.y);
        __half2 vB = __hadd2(*(__half2*)&ts.w, *(__half2*)&td.w);

        unsigned int efu = *(unsigned int*)&efh;
#pragma unroll
        for (int k = 0; k < 5; k++) {
            unsigned int eku = __shfl_sync(0xffffffffu, efu, base + k);
            __half2 ekh = *(__half2*)&eku;
            uA = __hfma2(ekh, wehA[k], uA);
            uB = __hfma2(ekh, wehB[k], uB);
            vA = __hfma2(ekh, wlhA[k], vA);
            vB = __hfma2(ekh, wlhB[k], vB);
        }
        float2 u0 = __half22float2(uA);
        float2 u1 = __half22float2(uB);
        float part = tanh_fast(u0.x) * we2v.x + tanh_fast(u0.y) * we2v.y
                   + tanh_fast(u1.x) * we2v.z + tanh_fast(u1.y) * we2v.w;
#pragma unroll
        for (int o = 8; o > 0; o >>= 1) part += __shfl_xor_sync(0xffffffffu, part, o);
        float wgt = 1.f / (1.f + __expf(-(part + be2v)));
        float2 v0 = __half22float2(vA);
        float2 v1 = __half22float2(vB);
        float o0 = fmaxf(fmaf(wgt, v0.x, bl1v.x), 0.f);
        float o1 = fmaxf(fmaf(wgt, v0.y, bl1v.y), 0.f);
        float o2 = fmaxf(fmaf(wgt, v1.x, bl1v.z), 0.f);
        float o3 = fmaxf(fmaf(wgt, v1.y, bl1v.w), 0.f);
        float p2 = o0 * wl2v.x + o1 * wl2v.y + o2 * wl2v.z + o3 * wl2v.w;
#pragma unroll
        for (int o = 8; o > 0; o >>= 1) p2 += __shfl_xor_sync(0xffffffffu, p2, o);
        if (li == 0) out[ecur] = p2 + bl2v;
    }
}

// ---------------- launch -----------------------------------------------------
extern "C" void kernel_launch(void* const* d_in, const int* in_sizes, int n_in,
                              void* d_out, int out_size) {
    const float* node_feat = (const float*)d_in[0];
    const float* edge_feat = (const float*)d_in[1];
    const int*   src       = (const int*)d_in[2];
    const int*   dst       = (const int*)d_in[3];
    const float* W1s = (const float*)d_in[4];
    const float* W1n = (const float*)d_in[5];
    const float* b1  = (const float*)d_in[6];
    const float* W2s = (const float*)d_in[7];
    const float* W2n = (const float*)d_in[8];
    const float* b2  = (const float*)d_in[9];
    const float* Wnp = (const float*)d_in[10];
    const float* bnp = (const float*)d_in[11];
    const float* We1 = (const float*)d_in[12];
    const float* be1 = (const float*)d_in[13];
    const float* We2 = (const float*)d_in[14];
    const float* be2 = (const float*)d_in[15];
    const float* Wl1 = (const float*)d_in[16];
    const float* bl1 = (const float*)d_in[17];
    const float* Wl2 = (const float*)d_in[18];
    const float* bl2 = (const float*)d_in[19];
    float* out = (float*)d_out;

    float *ph1, *ph2;
    void *pst, *pdt, *pdeg, *pcnt;
    cudaGetSymbolAddress((void**)&ph1, g_h1);
    cudaGetSymbolAddress((void**)&ph2, g_h2);
    cudaGetSymbolAddress(&pst,  g_srct);
    cudaGetSymbolAddress(&pdt,  g_dstt);
    cudaGetSymbolAddress(&pdeg, g_deg);
    cudaGetSymbolAddress(&pcnt, g_cnt);

    int nb   = (NN + 1023) / 1024;
    int nblk = (NN + 7) / 8;          // warp-per-node kernels
    int wblk = (NN + 127) / 128;      // WMMA kernels (128 nodes/block)

    cudaMemsetAsync(pdeg, 0, NN * sizeof(int));
    cudaMemsetAsync(pcnt, 0, NN * sizeof(int));
    k_deg<<<(NE + 255) / 256, 256>>>(dst);
    k_scan1<<<nb, 1024>>>();
    k_scan2<<<1, 128>>>(nb);
    k_scan3<<<(NN + 255) / 256, 256>>>();
    k_scatter<<<(NE + 255) / 256, 256>>>(src, dst);

    // Layer 1
    k_proj1<<<(NN * 32 + 255) / 256, 256>>>(node_feat, W1n);
    k_sage1<<<nblk, 256>>>(node_feat, W1s, b1);

    // Layer 2: p2 = h1@W2n (half2) AND h1@W2s (fp32) via WMMA, then combine
    k_wdual<<<wblk, 256>>>(ph1, W2n, W2s, ph2);
    k_sage2b<<<nblk, 256>>>(b2);

    // hp = relu(h2@Wnp + bnp) into g_h1 (WMMA)
    k_wbias<<<wblk, 256>>>(ph2, Wnp, bnp, ph1);

    // per-node interleaved half2 tables (both roles in one launch)
    dim3 tgrid(wblk, 2);
    k_wtab<<<tgrid, 256>>>(ph1, We1, Wl1, (unsigned int*)pst, (unsigned int*)pdt);

    // persistent fused edge stage: 16 lanes/edge, 2 edges/warp, half2 math
    k_edge<<<1184, 256>>>(src, dst, edge_feat,
                          We1, be1, We2, be2, Wl1, bl1, Wl2, bl2, out);
}

// round 10
// speedup vs baseline: 1.6261x; 1.0345x over previous
#include <cuda_runtime.h>
#include <cuda_fp16.h>
#include <mma.h>

#define NN 100000
#define NE 1600000
#define HD 64

namespace wm = nvcuda::wmma;

// ---------------- scratch (device globals; no allocation allowed) ----------
__device__ int   g_dc[2 * NN];       // [0:NN)=deg, [NN:2NN)=cnt
__device__ float g_inv[NN];
__device__ int   g_off[NN + 1];
__device__ int   g_bsum[128];
__device__ int   g_csr_src[NE];
__device__ __half2 g_p16[NN * 32];   // projected neighbor features (half2 pairs)
__device__ float g_h1[NN * HD];      // h1
__device__ float g_h2[NN * HD];      // h2
// per-node tables, 16B-aligned: 16 x uint4 per node; as uint2[32]:
// idx j = {We-pair(feats 2j,2j+1) , Wl-pair} interleaved
__device__ uint4 g_srct[NN * 16];
__device__ uint4 g_dstt[NN * 16];

__device__ __forceinline__ float tanh_fast(float x) {
    float y;
    asm("tanh.approx.f32 %0, %1;" : "=f"(y) : "f"(x));
    return y;
}

// ---------------- degree histogram -----------------------------------------
__global__ void k_deg(const int* __restrict__ dst) {
    int e = blockIdx.x * blockDim.x + threadIdx.x;
    if (e < NE) atomicAdd(&g_dc[dst[e]], 1);
}

// ---------------- exclusive scan (3 kernels) --------------------------------
__global__ void k_scan1() {
    __shared__ int sh[1024];
    int tid = threadIdx.x;
    int i = blockIdx.x * 1024 + tid;
    int v = (i < NN) ? g_dc[i] : 0;
    sh[tid] = v;
    __syncthreads();
    for (int o = 1; o < 1024; o <<= 1) {
        int t = (tid >= o) ? sh[tid - o] : 0;
        __syncthreads();
        sh[tid] += t;
        __syncthreads();
    }
    if (i < NN) g_off[i] = sh[tid] - v;
    if (tid == 1023) g_bsum[blockIdx.x] = sh[1023];
}

__global__ void k_scan2(int nb) {
    __shared__ int sh[128];
    int tid = threadIdx.x;
    int v = (tid < nb) ? g_bsum[tid] : 0;
    sh[tid] = v;
    __syncthreads();
    for (int o = 1; o < 128; o <<= 1) {
        int t = (tid >= o) ? sh[tid - o] : 0;
        __syncthreads();
        sh[tid] += t;
        __syncthreads();
    }
    g_bsum[tid] = sh[tid] - v;
    if (tid == 127) g_off[NN] = sh[127];
}

__global__ void k_scan3() {
    int i = blockIdx.x * blockDim.x + threadIdx.x;
    if (i < NN) {
        g_off[i] += g_bsum[i >> 10];
        int d = g_dc[i];
        g_inv[i] = 1.0f / (float)(d > 0 ? d : 1);
    }
}

// ---------------- CSR scatter ------------------------------------------------
__global__ void k_scatter(const int* __restrict__ src, const int* __restrict__ dst) {
    int e = blockIdx.x * blockDim.x + threadIdx.x;
    if (e < NE) {
        int d = dst[e];
        int pos = atomicAdd(&g_dc[NN + d], 1);
        g_csr_src[g_off[d] + pos] = src[e];
    }
}

// ---------------- p1 = node_feat @ W1n  (4 x 64) -> half2 -------------------
__global__ void k_proj1(const float* __restrict__ nf, const float* __restrict__ W) {
    __shared__ float sW[4 * HD];
    int tid = threadIdx.x;
    sW[tid] = W[tid];
    __syncthreads();
    int idx = blockIdx.x * 256 + tid;
    if (idx >= NN * 32) return;
    int n = idx >> 5, j = idx & 31;
    const float* r = &nf[n * 4];
    float r0 = r[0], r1 = r[1], r2 = r[2], r3 = r[3];
    float v0 = r0 * sW[2*j]   + r1 * sW[64 + 2*j]   + r2 * sW[128 + 2*j]   + r3 * sW[192 + 2*j];
    float v1 = r0 * sW[2*j+1] + r1 * sW[64 + 2*j+1] + r2 * sW[128 + 2*j+1] + r3 * sW[192 + 2*j+1];
    g_p16[idx] = __floats2half2_rn(v0, v1);
}

// ---------------- SAGE layer 1 ----------------------------------------------
__global__ void k_sage1(const float* __restrict__ nf, const float* __restrict__ Ws,
                        const float* __restrict__ b) {
    __shared__ float sW[4 * HD];
    int tid = threadIdx.x;
    sW[tid] = Ws[tid];
    __syncthreads();
    int n = blockIdx.x * 8 + (tid >> 5);
    int l = tid & 31;
    if (n >= NN) return;
    int beg = g_off[n], end = g_off[n + 1];
    float ax = 0.f, ay = 0.f;
    int j = beg;
    for (; j + 4 <= end; j += 4) {
        int s0 = g_csr_src[j], s1 = g_csr_src[j + 1];
        int s2 = g_csr_src[j + 2], s3 = g_csr_src[j + 3];
        float2 q0 = __half22float2(g_p16[s0 * 32 + l]);
        float2 q1 = __half22float2(g_p16[s1 * 32 + l]);
        float2 q2 = __half22float2(g_p16[s2 * 32 + l]);
        float2 q3 = __half22float2(g_p16[s3 * 32 + l]);
        ax += (q0.x + q1.x) + (q2.x + q3.x);
        ay += (q0.y + q1.y) + (q2.y + q3.y);
    }
    for (; j < end; j++) {
        float2 q = __half22float2(g_p16[g_csr_src[j] * 32 + l]);
        ax += q.x; ay += q.y;
    }
    float iv = g_inv[n];
    const float* r = &nf[n * 4];
    float n0 = r[0], n1 = r[1], n2 = r[2], n3 = r[3];
    float sx = n0*sW[2*l]   + n1*sW[64+2*l]   + n2*sW[128+2*l]   + n3*sW[192+2*l];
    float sy = n0*sW[2*l+1] + n1*sW[64+2*l+1] + n2*sW[128+2*l+1] + n3*sW[192+2*l+1];
    float2 o;
    o.x = fmaxf(sx + ax * iv + b[2*l],     0.f);
    o.y = fmaxf(sy + ay * iv + b[2*l+1],   0.f);
    *(float2*)&g_h1[(size_t)n * HD + 2*l] = o;
}

// ================= WMMA GEMM stages (fp16 in, fp32 accum) ===================

// ---- dual: p16 = X@Wn (half2), outf = X@Ws (fp32), no bias ----------------
__global__ void k_wdual(const float* __restrict__ in, const float* __restrict__ Wn,
                        const float* __restrict__ Ws, float* __restrict__ outf) {
    __shared__ __align__(32) __half Xh[128 * HD];
    __shared__ __align__(32) __half WA[HD * HD];
    __shared__ __align__(32) __half WB[HD * HD];
    __shared__ float scr[8][256];
    int tid = threadIdx.x, w = tid >> 5, lane = tid & 31;
    int nbase = blockIdx.x * 128;
    int base = nbase * HD;
    for (int t = tid; t < 128 * HD; t += 256) {
        int gi = base + t;
        Xh[t] = (gi < NN * HD) ? __float2half(in[gi]) : __half(0.f);
    }
    for (int t = tid; t < HD * HD; t += 256) {
        WA[t] = __float2half(Wn[t]);
        WB[t] = __float2half(Ws[t]);
    }
    __syncthreads();
    int r0 = w * 16;
#pragma unroll
    for (int nt = 0; nt < 4; nt++) {
        wm::fragment<wm::accumulator, 16, 16, 16, float> accA, accB;
        wm::fill_fragment(accA, 0.f);
        wm::fill_fragment(accB, 0.f);
#pragma unroll
        for (int kt = 0; kt < 4; kt++) {
            wm::fragment<wm::matrix_a, 16, 16, 16, __half, wm::row_major> a;
            wm::fragment<wm::matrix_b, 16, 16, 16, __half, wm::row_major> bA, bB;
            wm::load_matrix_sync(a, Xh + r0 * HD + kt * 16, HD);
            wm::load_matrix_sync(bA, WA + kt * 16 * HD + nt * 16, HD);
            wm::load_matrix_sync(bB, WB + kt * 16 * HD + nt * 16, HD);
            wm::mma_sync(accA, a, bA, accA);
            wm::mma_sync(accB, a, bB, accB);
        }
        wm::store_matrix_sync(scr[w], accB, 16, wm::mem_row_major);
        __syncwarp();
        for (int t = lane; t < 256; t += 32) {
            int row = t >> 4, col = t & 15;
            int n = nbase + r0 + row;
            if (n < NN) outf[(size_t)n * HD + nt * 16 + col] = scr[w][t];
        }
        __syncwarp();
        wm::store_matrix_sync(scr[w], accA, 16, wm::mem_row_major);
        __syncwarp();
        for (int t = lane; t < 128; t += 32) {
            int row = t >> 3, cp = t & 7;
            int n = nbase + r0 + row;
            if (n < NN)
                g_p16[(size_t)n * 32 + nt * 8 + cp] =
                    __floats2half2_rn(scr[w][row * 16 + 2 * cp], scr[w][row * 16 + 2 * cp + 1]);
        }
        __syncwarp();
    }
}

// ---- fused: hp = relu(h2@Wnp + bnp) in smem, then both role table GEMMs ----
// smem = Xh(16K) + Yh(16K) + WA(8K) + WB(8K) = 48K exactly.
// phase1 staging aliases WB; phase2 staging aliases Xh.
__global__ void k_wfuse(const float* __restrict__ h2in, const float* __restrict__ Wnp,
                        const float* __restrict__ bnp,
                        const float* __restrict__ We1, const float* __restrict__ Wl1,
                        unsigned int* __restrict__ utab_s, unsigned int* __restrict__ utab_d) {
    __shared__ __align__(32) __half Xh[128 * HD];   // phase1 A operand / phase2 scratch
    __shared__ __align__(32) __half Yh[128 * HD];   // hp tile (phase2 A operand)
    __shared__ __align__(32) __half WA[HD * HD];
    __shared__ __align__(32) __half WB[HD * HD];    // phase1 scratch / phase2 Wl weights
    int tid = threadIdx.x, w = tid >> 5, lane = tid & 31;
    int nbase = blockIdx.x * 128;
    int base = nbase * HD;
    for (int t = tid; t < 128 * HD; t += 256) {
        int gi = base + t;
        Xh[t] = (gi < NN * HD) ? __float2half(h2in[gi]) : __half(0.f);
    }
    for (int t = tid; t < HD * HD; t += 256) WA[t] = __float2half(Wnp[t]);
    __syncthreads();

    int r0 = w * 16;
    // ---- phase 1: hp tile into Yh ----
    {
        float* scr1 = (float*)WB;   // 8 warps x 256 floats
#pragma unroll
        for (int nt = 0; nt < 4; nt++) {
            wm::fragment<wm::accumulator, 16, 16, 16, float> acc;
            wm::fill_fragment(acc, 0.f);
#pragma unroll
            for (int kt = 0; kt < 4; kt++) {
                wm::fragment<wm::matrix_a, 16, 16, 16, __half, wm::row_major> a;
                wm::fragment<wm::matrix_b, 16, 16, 16, __half, wm::row_major> b;
                wm::load_matrix_sync(a, Xh + r0 * HD + kt * 16, HD);
                wm::load_matrix_sync(b, WA + kt * 16 * HD + nt * 16, HD);
                wm::mma_sync(acc, a, b, acc);
            }
            wm::store_matrix_sync(scr1 + w * 256, acc, 16, wm::mem_row_major);
            __syncwarp();
            for (int t = lane; t < 256; t += 32) {
                int row = t >> 4, col = t & 15;
                float v = scr1[w * 256 + t] + __ldg(&bnp[nt * 16 + col]);
                Yh[(r0 + row) * HD + nt * 16 + col] = __float2half(fmaxf(v, 0.f));
            }
            __syncwarp();
        }
    }
    __syncthreads();

    // ---- phase 2: two roles, tables from Yh ----
    float* scr2 = (float*)Xh;       // reuse Xh region
    for (int role = 0; role < 2; role++) {
        const float* Wa = We1 + role * 64 * HD;
        const float* Wb = Wl1 + role * 64 * HD;
        unsigned int* utab = role ? utab_d : utab_s;
        for (int t = tid; t < HD * HD; t += 256) {
            WA[t] = __float2half(Wa[t]);
            WB[t] = __float2half(Wb[t]);
        }
        __syncthreads();
#pragma unroll
        for (int nt = 0; nt < 4; nt++) {
            wm::fragment<wm::accumulator, 16, 16, 16, float> accA, accB;
            wm::fill_fragment(accA, 0.f);
            wm::fill_fragment(accB, 0.f);
#pragma unroll
            for (int kt = 0; kt < 4; kt++) {
                wm::fragment<wm::matrix_a, 16, 16, 16, __half, wm::row_major> a;
                wm::fragment<wm::matrix_b, 16, 16, 16, __half, wm::row_major> bA, bB;
                wm::load_matrix_sync(a, Yh + r0 * HD + kt * 16, HD);
                wm::load_matrix_sync(bA, WA + kt * 16 * HD + nt * 16, HD);
                wm::load_matrix_sync(bB, WB + kt * 16 * HD + nt * 16, HD);
                wm::mma_sync(accA, a, bA, accA);
                wm::mma_sync(accB, a, bB, accB);
            }
            wm::store_matrix_sync(scr2 + w * 256, accA, 16, wm::mem_row_major);
            __syncwarp();
            for (int t = lane; t < 128; t += 32) {
                int row = t >> 3, cp = t & 7;
                int n = nbase + r0 + row;
                if (n < NN) {
                    __half2 h = __floats2half2_rn(scr2[w * 256 + row * 16 + 2 * cp],
                                                  scr2[w * 256 + row * 16 + 2 * cp + 1]);
                    utab[((size_t)n * 32 + nt * 8 + cp) * 2] = *(unsigned int*)&h;
                }
            }
            __syncwarp();
            wm::store_matrix_sync(scr2 + w * 256, accB, 16, wm::mem_row_major);
            __syncwarp();
            for (int t = lane; t < 128; t += 32) {
                int row = t >> 3, cp = t & 7;
                int n = nbase + r0 + row;
                if (n < NN) {
                    __half2 h = __floats2half2_rn(scr2[w * 256 + row * 16 + 2 * cp],
                                                  scr2[w * 256 + row * 16 + 2 * cp + 1]);
                    utab[((size_t)n * 32 + nt * 8 + cp) * 2 + 1] = *(unsigned int*)&h;
                }
            }
            __syncwarp();
        }
        __syncthreads();
    }
}

// ---------------- SAGE layer 2 combine: h2 = relu(h2 + agg*inv + b2) --------
__global__ void k_sage2b(const float* __restrict__ b) {
    int tid = threadIdx.x;
    int n = blockIdx.x * 8 + (tid >> 5);
    int l = tid & 31;
    if (n >= NN) return;
    int beg = g_off[n], end = g_off[n + 1];
    float ax = 0.f, ay = 0.f;
    int j = beg;
    for (; j + 4 <= end; j += 4) {
        int s0 = g_csr_src[j], s1 = g_csr_src[j + 1];
        int s2 = g_csr_src[j + 2], s3 = g_csr_src[j + 3];
        float2 q0 = __half22float2(g_p16[s0 * 32 + l]);
        float2 q1 = __half22float2(g_p16[s1 * 32 + l]);
        float2 q2 = __half22float2(g_p16[s2 * 32 + l]);
        float2 q3 = __half22float2(g_p16[s3 * 32 + l]);
        ax += (q0.x + q1.x) + (q2.x + q3.x);
        ay += (q0.y + q1.y) + (q2.y + q3.y);
    }
    for (; j < end; j++) {
        float2 q = __half22float2(g_p16[g_csr_src[j] * 32 + l]);
        ax += q.x; ay += q.y;
    }
    float iv = g_inv[n];
    float2 t = *(const float2*)&g_h2[(size_t)n * HD + 2 * l];
    float2 o;
    o.x = fmaxf(t.x + ax * iv + b[2 * l],     0.f);
    o.y = fmaxf(t.y + ay * iv + b[2 * l + 1], 0.f);
    *(float2*)&g_h2[(size_t)n * HD + 2 * l] = o;
}

// ------- edge kernel: 16 lanes/edge, 2 edges/warp, half2 + split chains -----
__global__ void k_edge(const int* __restrict__ src, const int* __restrict__ dst,
                       const float* __restrict__ ef,
                       const float* __restrict__ We1, const float* __restrict__ be1,
                       const float* __restrict__ We2, const float* __restrict__ be2,
                       const float* __restrict__ Wl1, const float* __restrict__ bl1,
                       const float* __restrict__ Wl2, const float* __restrict__ bl2,
                       float* __restrict__ out) {
    int tid = threadIdx.x;
    int l = tid & 31;
    int li = l & 15;            // lane within 16-lane edge group
    int g = l >> 4;             // which of the 2 edges
    int base = l & 16;          // shfl base for my group
    int warp = (blockIdx.x * blockDim.x + tid) >> 5;
    int nw = (gridDim.x * blockDim.x) >> 5;

    __half2 wehA[5], wehB[5], wlhA[5], wlhB[5];
#pragma unroll
    for (int k = 0; k < 5; k++) {
        float4 we = *(const float4*)&We1[(128 + k) * HD + 4 * li];
        float4 wl = *(const float4*)&Wl1[(128 + k) * HD + 4 * li];
        wehA[k] = __floats2half2_rn(we.x, we.y);
        wehB[k] = __floats2half2_rn(we.z, we.w);
        wlhA[k] = __floats2half2_rn(wl.x, wl.y);
        wlhB[k] = __floats2half2_rn(wl.z, wl.w);
    }
    float4 be1f = *(const float4*)&be1[4 * li];
    __half2 be1hA = __floats2half2_rn(be1f.x, be1f.y);
    __half2 be1hB = __floats2half2_rn(be1f.z, be1f.w);
    float4 bl1v = *(const float4*)&bl1[4 * li];
    float4 we2v = *(const float4*)&We2[4 * li];
    float4 wl2v = *(const float4*)&Wl2[4 * li];
    float be2v = be2[0], bl2v = bl2[0];

    int e = warp * 2 + g;
    int s = 0, d = 0;
    float efl = 0.f;
    if (e < NE) {
        s = __ldg(&src[e]);
        d = __ldg(&dst[e]);
        efl = (li < 5) ? __ldg(&ef[(size_t)e * 5 + li]) : 0.f;
    }
    for (int eb = warp * 2; eb < NE; eb += 2 * nw) {
        uint4 ts = *(const uint4*)((const uint2*)&g_srct[(size_t)s * 16] + 2 * li);
        uint4 td = *(const uint4*)((const uint2*)&g_dstt[(size_t)d * 16] + 2 * li);
        __half2 efh = __float2half2_rn(efl);
        int ecur = eb + g;

        // prefetch next iteration's indices/features
        int enext = eb + 2 * nw + g;
        if (enext < NE) {
            s = __ldg(&src[enext]);
            d = __ldg(&dst[enext]);
            efl = (li < 5) ? __ldg(&ef[(size_t)enext * 5 + li]) : 0.f;
        }

        // table sums (short chain 1)
        __half2 tA  = __hadd2(__hadd2(*(__half2*)&ts.x, *(__half2*)&td.x), be1hA);
        __half2 tB  = __hadd2(__hadd2(*(__half2*)&ts.z, *(__half2*)&td.z), be1hB);
        __half2 tvA = __hadd2(*(__half2*)&ts.y, *(__half2*)&td.y);
        __half2 tvB = __hadd2(*(__half2*)&ts.w, *(__half2*)&td.w);

        // ef x W chains (short chain 2), seeded by hmul2
        unsigned int efu = *(unsigned int*)&efh;
        unsigned int eku = __shfl_sync(0xffffffffu, efu, base);
        __half2 ekh = *(__half2*)&eku;
        __half2 cA = __hmul2(ekh, wehA[0]);
        __half2 cB = __hmul2(ekh, wehB[0]);
        __half2 dA = __hmul2(ekh, wlhA[0]);
        __half2 dB = __hmul2(ekh, wlhB[0]);
#pragma unroll
        for (int k = 1; k < 5; k++) {
            eku = __shfl_sync(0xffffffffu, efu, base + k);
            ekh = *(__half2*)&eku;
            cA = __hfma2(ekh, wehA[k], cA);
            cB = __hfma2(ekh, wehB[k], cB);
            dA = __hfma2(ekh, wlhA[k], dA);
            dB = __hfma2(ekh, wlhB[k], dB);
        }
        // combine chains in fp32
        float2 tAf = __half22float2(tA), cAf = __half22float2(cA);
        float2 tBf = __half22float2(tB), cBf = __half22float2(cB);
        float u0x = tAf.x + cAf.x, u0y = tAf.y + cAf.y;
        float u1x = tBf.x + cBf.x, u1y = tBf.y + cBf.y;
        float part = tanh_fast(u0x) * we2v.x + tanh_fast(u0y) * we2v.y
                   + tanh_fast(u1x) * we2v.z + tanh_fast(u1y) * we2v.w;
#pragma unroll
        for (int o = 8; o > 0; o >>= 1) part += __shfl_xor_sync(0xffffffffu, part, o);
        float wgt = 1.f / (1.f + __expf(-(part + be2v)));
        float2 tvAf = __half22float2(tvA), dAf = __half22float2(dA);
        float2 tvBf = __half22float2(tvB), dBf = __half22float2(dB);
        float v0 = tvAf.x + dAf.x, v1 = tvAf.y + dAf.y;
        float v2 = tvBf.x + dBf.x, v3 = tvBf.y + dBf.y;
        float o0 = fmaxf(fmaf(wgt, v0, bl1v.x), 0.f);
        float o1 = fmaxf(fmaf(wgt, v1, bl1v.y), 0.f);
        float o2 = fmaxf(fmaf(wgt, v2, bl1v.z), 0.f);
        float o3 = fmaxf(fmaf(wgt, v3, bl1v.w), 0.f);
        float p2 = o0 * wl2v.x + o1 * wl2v.y + o2 * wl2v.z + o3 * wl2v.w;
#pragma unroll
        for (int o = 8; o > 0; o >>= 1) p2 += __shfl_xor_sync(0xffffffffu, p2, o);
        if (li == 0) out[ecur] = p2 + bl2v;
    }
}

// ---------------- launch -----------------------------------------------------
extern "C" void kernel_launch(void* const* d_in, const int* in_sizes, int n_in,
                              void* d_out, int out_size) {
    const float* node_feat = (const float*)d_in[0];
    const float* edge_feat = (const float*)d_in[1];
    const int*   src       = (const int*)d_in[2];
    const int*   dst       = (const int*)d_in[3];
    const float* W1s = (const float*)d_in[4];
    const float* W1n = (const float*)d_in[5];
    const float* b1  = (const float*)d_in[6];
    const float* W2s = (const float*)d_in[7];
    const float* W2n = (const float*)d_in[8];
    const float* b2  = (const float*)d_in[9];
    const float* Wnp = (const float*)d_in[10];
    const float* bnp = (const float*)d_in[11];
    const float* We1 = (const float*)d_in[12];
    const float* be1 = (const float*)d_in[13];
    const float* We2 = (const float*)d_in[14];
    const float* be2 = (const float*)d_in[15];
    const float* Wl1 = (const float*)d_in[16];
    const float* bl1 = (const float*)d_in[17];
    const float* Wl2 = (const float*)d_in[18];
    const float* bl2 = (const float*)d_in[19];
    float* out = (float*)d_out;

    float *ph1, *ph2;
    void *pst, *pdt, *pdc;
    cudaGetSymbolAddress((void**)&ph1, g_h1);
    cudaGetSymbolAddress((void**)&ph2, g_h2);
    cudaGetSymbolAddress(&pst, g_srct);
    cudaGetSymbolAddress(&pdt, g_dstt);
    cudaGetSymbolAddress(&pdc, g_dc);

    int nb   = (NN + 1023) / 1024;
    int nblk = (NN + 7) / 8;          // warp-per-node kernels
    int wblk = (NN + 127) / 128;      // WMMA kernels (128 nodes/block)

    cudaMemsetAsync(pdc, 0, 2 * NN * sizeof(int));
    k_deg<<<(NE + 255) / 256, 256>>>(dst);
    k_scan1<<<nb, 1024>>>();
    k_scan2<<<1, 128>>>(nb);
    k_scan3<<<(NN + 255) / 256, 256>>>();
    k_scatter<<<(NE + 255) / 256, 256>>>(src, dst);

    // Layer 1
    k_proj1<<<(NN * 32 + 255) / 256, 256>>>(node_feat, W1n);
    k_sage1<<<nblk, 256>>>(node_feat, W1s, b1);

    // Layer 2: p2 = h1@W2n (half2) AND h1@W2s (fp32) via WMMA, then combine
    k_wdual<<<wblk, 256>>>(ph1, W2n, W2s, ph2);
    k_sage2b<<<nblk, 256>>>(b2);

    // fused: hp = relu(h2@Wnp+bnp) in smem, then both role tables
    k_wfuse<<<wblk, 256>>>(ph2, Wnp, bnp, We1, Wl1,
                           (unsigned int*)pst, (unsigned int*)pdt);

    // persistent fused edge stage
    k_edge<<<1184, 256>>>(src, dst, edge_feat,
                          We1, be1, We2, be2, Wl1, bl1, Wl2, bl2, out);
}

// round 11
// speedup vs baseline: 1.7719x; 1.0897x over previous
#include <cuda_runtime.h>
#include <cuda_fp16.h>
#include <mma.h>

#define NN 100000
#define NE 1600000
#define HD 64

namespace wm = nvcuda::wmma;

// ---------------- scratch (device globals; no allocation allowed) ----------
__device__ int   g_dc[2 * NN];       // [0:NN)=deg, [NN:2NN)=cnt
__device__ float g_inv[NN];
__device__ int   g_off[NN + 1];
__device__ int   g_bsum[128];
__device__ int   g_csr_src[NE];
__device__ __half2 g_p16[NN * 32];   // projected neighbor features (half2 pairs)
__device__ float g_h1[NN * HD];      // h1
__device__ float g_h2[NN * HD];      // h2
// per-node tables, 16B-aligned: 16 x uint4 per node; as uint2[32]:
// idx j = {We-pair(feats 2j,2j+1) , Wl-pair} interleaved
__device__ uint4 g_srct[NN * 16];
__device__ uint4 g_dstt[NN * 16];

__device__ __forceinline__ float tanh_fast(float x) {
    float y;
    asm("tanh.approx.f32 %0, %1;" : "=f"(y) : "f"(x));
    return y;
}

// ---------------- degree histogram -----------------------------------------
__global__ void k_deg(const int* __restrict__ dst) {
    int e = blockIdx.x * blockDim.x + threadIdx.x;
    if (e < NE) atomicAdd(&g_dc[dst[e]], 1);
}

// ---------------- exclusive scan (3 kernels) --------------------------------
__global__ void k_scan1() {
    __shared__ int sh[1024];
    int tid = threadIdx.x;
    int i = blockIdx.x * 1024 + tid;
    int v = (i < NN) ? g_dc[i] : 0;
    sh[tid] = v;
    __syncthreads();
    for (int o = 1; o < 1024; o <<= 1) {
        int t = (tid >= o) ? sh[tid - o] : 0;
        __syncthreads();
        sh[tid] += t;
        __syncthreads();
    }
    if (i < NN) g_off[i] = sh[tid] - v;
    if (tid == 1023) g_bsum[blockIdx.x] = sh[1023];
}

__global__ void k_scan2(int nb) {
    __shared__ int sh[128];
    int tid = threadIdx.x;
    int v = (tid < nb) ? g_bsum[tid] : 0;
    sh[tid] = v;
    __syncthreads();
    for (int o = 1; o < 128; o <<= 1) {
        int t = (tid >= o) ? sh[tid - o] : 0;
        __syncthreads();
        sh[tid] += t;
        __syncthreads();
    }
    g_bsum[tid] = sh[tid] - v;
    if (tid == 127) g_off[NN] = sh[127];
}

__global__ void k_scan3() {
    int i = blockIdx.x * blockDim.x + threadIdx.x;
    if (i < NN) {
        g_off[i] += g_bsum[i >> 10];
        int d = g_dc[i];
        g_inv[i] = 1.0f / (float)(d > 0 ? d : 1);
    }
}

// ---------------- CSR scatter ------------------------------------------------
__global__ void k_scatter(const int* __restrict__ src, const int* __restrict__ dst) {
    int e = blockIdx.x * blockDim.x + threadIdx.x;
    if (e < NE) {
        int d = dst[e];
        int pos = atomicAdd(&g_dc[NN + d], 1);
        g_csr_src[g_off[d] + pos] = src[e];
    }
}

// ---------------- p1 = node_feat @ W1n  (4 x 64) -> half2 -------------------
__global__ void k_proj1(const float* __restrict__ nf, const float* __restrict__ W) {
    __shared__ float sW[4 * HD];
    int tid = threadIdx.x;
    sW[tid] = W[tid];
    __syncthreads();
    int idx = blockIdx.x * 256 + tid;
    if (idx >= NN * 32) return;
    int n = idx >> 5, j = idx & 31;
    const float* r = &nf[n * 4];
    float r0 = r[0], r1 = r[1], r2 = r[2], r3 = r[3];
    float v0 = r0 * sW[2*j]   + r1 * sW[64 + 2*j]   + r2 * sW[128 + 2*j]   + r3 * sW[192 + 2*j];
    float v1 = r0 * sW[2*j+1] + r1 * sW[64 + 2*j+1] + r2 * sW[128 + 2*j+1] + r3 * sW[192 + 2*j+1];
    g_p16[idx] = __floats2half2_rn(v0, v1);
}

// ---------------- SAGE layer 1 (MLP=8 gathers) ------------------------------
__global__ void k_sage1(const float* __restrict__ nf, const float* __restrict__ Ws,
                        const float* __restrict__ b) {
    __shared__ float sW[4 * HD];
    int tid = threadIdx.x;
    sW[tid] = Ws[tid];
    __syncthreads();
    int n = blockIdx.x * 8 + (tid >> 5);
    int l = tid & 31;
    if (n >= NN) return;
    int beg = g_off[n], end = g_off[n + 1];
    float ax = 0.f, ay = 0.f;
    int j = beg;
    for (; j + 8 <= end; j += 8) {
        int s0 = g_csr_src[j],     s1 = g_csr_src[j + 1];
        int s2 = g_csr_src[j + 2], s3 = g_csr_src[j + 3];
        int s4 = g_csr_src[j + 4], s5 = g_csr_src[j + 5];
        int s6 = g_csr_src[j + 6], s7 = g_csr_src[j + 7];
        float2 q0 = __half22float2(g_p16[s0 * 32 + l]);
        float2 q1 = __half22float2(g_p16[s1 * 32 + l]);
        float2 q2 = __half22float2(g_p16[s2 * 32 + l]);
        float2 q3 = __half22float2(g_p16[s3 * 32 + l]);
        float2 q4 = __half22float2(g_p16[s4 * 32 + l]);
        float2 q5 = __half22float2(g_p16[s5 * 32 + l]);
        float2 q6 = __half22float2(g_p16[s6 * 32 + l]);
        float2 q7 = __half22float2(g_p16[s7 * 32 + l]);
        ax += ((q0.x + q1.x) + (q2.x + q3.x)) + ((q4.x + q5.x) + (q6.x + q7.x));
        ay += ((q0.y + q1.y) + (q2.y + q3.y)) + ((q4.y + q5.y) + (q6.y + q7.y));
    }
    for (; j + 4 <= end; j += 4) {
        int s0 = g_csr_src[j],     s1 = g_csr_src[j + 1];
        int s2 = g_csr_src[j + 2], s3 = g_csr_src[j + 3];
        float2 q0 = __half22float2(g_p16[s0 * 32 + l]);
        float2 q1 = __half22float2(g_p16[s1 * 32 + l]);
        float2 q2 = __half22float2(g_p16[s2 * 32 + l]);
        float2 q3 = __half22float2(g_p16[s3 * 32 + l]);
        ax += (q0.x + q1.x) + (q2.x + q3.x);
        ay += (q0.y + q1.y) + (q2.y + q3.y);
    }
    for (; j < end; j++) {
        float2 q = __half22float2(g_p16[g_csr_src[j] * 32 + l]);
        ax += q.x; ay += q.y;
    }
    float iv = g_inv[n];
    const float* r = &nf[n * 4];
    float n0 = r[0], n1 = r[1], n2 = r[2], n3 = r[3];
    float sx = n0*sW[2*l]   + n1*sW[64+2*l]   + n2*sW[128+2*l]   + n3*sW[192+2*l];
    float sy = n0*sW[2*l+1] + n1*sW[64+2*l+1] + n2*sW[128+2*l+1] + n3*sW[192+2*l+1];
    float2 o;
    o.x = fmaxf(sx + ax * iv + b[2*l],     0.f);
    o.y = fmaxf(sy + ay * iv + b[2*l+1],   0.f);
    *(float2*)&g_h1[(size_t)n * HD + 2*l] = o;
}

// ================= WMMA GEMM stages (fp16 in, fp32 accum) ===================

// ---- dual: p16 = X@Wn (half2), outf = X@Ws (fp32), no bias ----------------
__global__ void k_wdual(const float* __restrict__ in, const float* __restrict__ Wn,
                        const float* __restrict__ Ws, float* __restrict__ outf) {
    __shared__ __align__(32) __half Xh[128 * HD];
    __shared__ __align__(32) __half WA[HD * HD];
    __shared__ __align__(32) __half WB[HD * HD];
    __shared__ float scr[8][256];
    int tid = threadIdx.x, w = tid >> 5, lane = tid & 31;
    int nbase = blockIdx.x * 128;
    int base = nbase * HD;
    for (int t = tid; t < 128 * HD; t += 256) {
        int gi = base + t;
        Xh[t] = (gi < NN * HD) ? __float2half(in[gi]) : __half(0.f);
    }
    for (int t = tid; t < HD * HD; t += 256) {
        WA[t] = __float2half(Wn[t]);
        WB[t] = __float2half(Ws[t]);
    }
    __syncthreads();
    int r0 = w * 16;
#pragma unroll
    for (int nt = 0; nt < 4; nt++) {
        wm::fragment<wm::accumulator, 16, 16, 16, float> accA, accB;
        wm::fill_fragment(accA, 0.f);
        wm::fill_fragment(accB, 0.f);
#pragma unroll
        for (int kt = 0; kt < 4; kt++) {
            wm::fragment<wm::matrix_a, 16, 16, 16, __half, wm::row_major> a;
            wm::fragment<wm::matrix_b, 16, 16, 16, __half, wm::row_major> bA, bB;
            wm::load_matrix_sync(a, Xh + r0 * HD + kt * 16, HD);
            wm::load_matrix_sync(bA, WA + kt * 16 * HD + nt * 16, HD);
            wm::load_matrix_sync(bB, WB + kt * 16 * HD + nt * 16, HD);
            wm::mma_sync(accA, a, bA, accA);
            wm::mma_sync(accB, a, bB, accB);
        }
        wm::store_matrix_sync(scr[w], accB, 16, wm::mem_row_major);
        __syncwarp();
        for (int t = lane; t < 256; t += 32) {
            int row = t >> 4, col = t & 15;
            int n = nbase + r0 + row;
            if (n < NN) outf[(size_t)n * HD + nt * 16 + col] = scr[w][t];
        }
        __syncwarp();
        wm::store_matrix_sync(scr[w], accA, 16, wm::mem_row_major);
        __syncwarp();
        for (int t = lane; t < 128; t += 32) {
            int row = t >> 3, cp = t & 7;
            int n = nbase + r0 + row;
            if (n < NN)
                g_p16[(size_t)n * 32 + nt * 8 + cp] =
                    __floats2half2_rn(scr[w][row * 16 + 2 * cp], scr[w][row * 16 + 2 * cp + 1]);
        }
        __syncwarp();
    }
}

// ---- fused: hp = relu(h2@Wnp + bnp) in smem, then both role table GEMMs ----
__global__ void k_wfuse(const float* __restrict__ h2in, const float* __restrict__ Wnp,
                        const float* __restrict__ bnp,
                        const float* __restrict__ We1, const float* __restrict__ Wl1,
                        unsigned int* __restrict__ utab_s, unsigned int* __restrict__ utab_d) {
    __shared__ __align__(32) __half Xh[128 * HD];   // phase1 A operand / phase2 scratch
    __shared__ __align__(32) __half Yh[128 * HD];   // hp tile (phase2 A operand)
    __shared__ __align__(32) __half WA[HD * HD];
    __shared__ __align__(32) __half WB[HD * HD];    // phase1 scratch / phase2 Wl weights
    int tid = threadIdx.x, w = tid >> 5, lane = tid & 31;
    int nbase = blockIdx.x * 128;
    int base = nbase * HD;
    for (int t = tid; t < 128 * HD; t += 256) {
        int gi = base + t;
        Xh[t] = (gi < NN * HD) ? __float2half(h2in[gi]) : __half(0.f);
    }
    for (int t = tid; t < HD * HD; t += 256) WA[t] = __float2half(Wnp[t]);
    __syncthreads();

    int r0 = w * 16;
    // ---- phase 1: hp tile into Yh ----
    {
        float* scr1 = (float*)WB;
#pragma unroll
        for (int nt = 0; nt < 4; nt++) {
            wm::fragment<wm::accumulator, 16, 16, 16, float> acc;
            wm::fill_fragment(acc, 0.f);
#pragma unroll
            for (int kt = 0; kt < 4; kt++) {
                wm::fragment<wm::matrix_a, 16, 16, 16, __half, wm::row_major> a;
                wm::fragment<wm::matrix_b, 16, 16, 16, __half, wm::row_major> b;
                wm::load_matrix_sync(a, Xh + r0 * HD + kt * 16, HD);
                wm::load_matrix_sync(b, WA + kt * 16 * HD + nt * 16, HD);
                wm::mma_sync(acc, a, b, acc);
            }
            wm::store_matrix_sync(scr1 + w * 256, acc, 16, wm::mem_row_major);
            __syncwarp();
            for (int t = lane; t < 256; t += 32) {
                int row = t >> 4, col = t & 15;
                float v = scr1[w * 256 + t] + __ldg(&bnp[nt * 16 + col]);
                Yh[(r0 + row) * HD + nt * 16 + col] = __float2half(fmaxf(v, 0.f));
            }
            __syncwarp();
        }
    }
    __syncthreads();

    // ---- phase 2: two roles, tables from Yh ----
    float* scr2 = (float*)Xh;
    for (int role = 0; role < 2; role++) {
        const float* Wa = We1 + role * 64 * HD;
        const float* Wb = Wl1 + role * 64 * HD;
        unsigned int* utab = role ? utab_d : utab_s;
        for (int t = tid; t < HD * HD; t += 256) {
            WA[t] = __float2half(Wa[t]);
            WB[t] = __float2half(Wb[t]);
        }
        __syncthreads();
#pragma unroll
        for (int nt = 0; nt < 4; nt++) {
            wm::fragment<wm::accumulator, 16, 16, 16, float> accA, accB;
            wm::fill_fragment(accA, 0.f);
            wm::fill_fragment(accB, 0.f);
#pragma unroll
            for (int kt = 0; kt < 4; kt++) {
                wm::fragment<wm::matrix_a, 16, 16, 16, __half, wm::row_major> a;
                wm::fragment<wm::matrix_b, 16, 16, 16, __half, wm::row_major> bA, bB;
                wm::load_matrix_sync(a, Yh + r0 * HD + kt * 16, HD);
                wm::load_matrix_sync(bA, WA + kt * 16 * HD + nt * 16, HD);
                wm::load_matrix_sync(bB, WB + kt * 16 * HD + nt * 16, HD);
                wm::mma_sync(accA, a, bA, accA);
                wm::mma_sync(accB, a, bB, accB);
            }
            wm::store_matrix_sync(scr2 + w * 256, accA, 16, wm::mem_row_major);
            __syncwarp();
            for (int t = lane; t < 128; t += 32) {
                int row = t >> 3, cp = t & 7;
                int n = nbase + r0 + row;
                if (n < NN) {
                    __half2 h = __floats2half2_rn(scr2[w * 256 + row * 16 + 2 * cp],
                                                  scr2[w * 256 + row * 16 + 2 * cp + 1]);
                    utab[((size_t)n * 32 + nt * 8 + cp) * 2] = *(unsigned int*)&h;
                }
            }
            __syncwarp();
            wm::store_matrix_sync(scr2 + w * 256, accB, 16, wm::mem_row_major);
            __syncwarp();
            for (int t = lane; t < 128; t += 32) {
                int row = t >> 3, cp = t & 7;
                int n = nbase + r0 + row;
                if (n < NN) {
                    __half2 h = __floats2half2_rn(scr2[w * 256 + row * 16 + 2 * cp],
                                                  scr2[w * 256 + row * 16 + 2 * cp + 1]);
                    utab[((size_t)n * 32 + nt * 8 + cp) * 2 + 1] = *(unsigned int*)&h;
                }
            }
            __syncwarp();
        }
        __syncthreads();
    }
}

// ---------------- SAGE layer 2 combine (MLP=8 gathers) -----------------------
__global__ void k_sage2b(const float* __restrict__ b) {
    int tid = threadIdx.x;
    int n = blockIdx.x * 8 + (tid >> 5);
    int l = tid & 31;
    if (n >= NN) return;
    int beg = g_off[n], end = g_off[n + 1];
    float ax = 0.f, ay = 0.f;
    int j = beg;
    for (; j + 8 <= end; j += 8) {
        int s0 = g_csr_src[j],     s1 = g_csr_src[j + 1];
        int s2 = g_csr_src[j + 2], s3 = g_csr_src[j + 3];
        int s4 = g_csr_src[j + 4], s5 = g_csr_src[j + 5];
        int s6 = g_csr_src[j + 6], s7 = g_csr_src[j + 7];
        float2 q0 = __half22float2(g_p16[s0 * 32 + l]);
        float2 q1 = __half22float2(g_p16[s1 * 32 + l]);
        float2 q2 = __half22float2(g_p16[s2 * 32 + l]);
        float2 q3 = __half22float2(g_p16[s3 * 32 + l]);
        float2 q4 = __half22float2(g_p16[s4 * 32 + l]);
        float2 q5 = __half22float2(g_p16[s5 * 32 + l]);
        float2 q6 = __half22float2(g_p16[s6 * 32 + l]);
        float2 q7 = __half22float2(g_p16[s7 * 32 + l]);
        ax += ((q0.x + q1.x) + (q2.x + q3.x)) + ((q4.x + q5.x) + (q6.x + q7.x));
        ay += ((q0.y + q1.y) + (q2.y + q3.y)) + ((q4.y + q5.y) + (q6.y + q7.y));
    }
    for (; j + 4 <= end; j += 4) {
        int s0 = g_csr_src[j],     s1 = g_csr_src[j + 1];
        int s2 = g_csr_src[j + 2], s3 = g_csr_src[j + 3];
        float2 q0 = __half22float2(g_p16[s0 * 32 + l]);
        float2 q1 = __half22float2(g_p16[s1 * 32 + l]);
        float2 q2 = __half22float2(g_p16[s2 * 32 + l]);
        float2 q3 = __half22float2(g_p16[s3 * 32 + l]);
        ax += (q0.x + q1.x) + (q2.x + q3.x);
        ay += (q0.y + q1.y) + (q2.y + q3.y);
    }
    for (; j < end; j++) {
        float2 q = __half22float2(g_p16[g_csr_src[j] * 32 + l]);
        ax += q.x; ay += q.y;
    }
    float iv = g_inv[n];
    float2 t = *(const float2*)&g_h2[(size_t)n * HD + 2 * l];
    float2 o;
    o.x = fmaxf(t.x + ax * iv + b[2 * l],     0.f);
    o.y = fmaxf(t.y + ay * iv + b[2 * l + 1], 0.f);
    *(float2*)&g_h2[(size_t)n * HD + 2 * l] = o;
}

// ------- edge kernel: 16 lanes/edge, 2 edges/warp, half2 + half2 v-epilogue --
__global__ void k_edge(const int* __restrict__ src, const int* __restrict__ dst,
                       const float* __restrict__ ef,
                       const float* __restrict__ We1, const float* __restrict__ be1,
                       const float* __restrict__ We2, const float* __restrict__ be2,
                       const float* __restrict__ Wl1, const float* __restrict__ bl1,
                       const float* __restrict__ Wl2, const float* __restrict__ bl2,
                       float* __restrict__ out) {
    int tid = threadIdx.x;
    int l = tid & 31;
    int li = l & 15;            // lane within 16-lane edge group
    int g = l >> 4;             // which of the 2 edges
    int base = l & 16;          // shfl base for my group
    int warp = (blockIdx.x * blockDim.x + tid) >> 5;
    int nw = (gridDim.x * blockDim.x) >> 5;

    __half2 wehA[5], wehB[5], wlhA[5], wlhB[5];
#pragma unroll
    for (int k = 0; k < 5; k++) {
        float4 we = *(const float4*)&We1[(128 + k) * HD + 4 * li];
        float4 wl = *(const float4*)&Wl1[(128 + k) * HD + 4 * li];
        wehA[k] = __floats2half2_rn(we.x, we.y);
        wehB[k] = __floats2half2_rn(we.z, we.w);
        wlhA[k] = __floats2half2_rn(wl.x, wl.y);
        wlhB[k] = __floats2half2_rn(wl.z, wl.w);
    }
    float4 be1f = *(const float4*)&be1[4 * li];
    __half2 be1hA = __floats2half2_rn(be1f.x, be1f.y);
    __half2 be1hB = __floats2half2_rn(be1f.z, be1f.w);
    float4 bl1f = *(const float4*)&bl1[4 * li];
    __half2 bl1hA = __floats2half2_rn(bl1f.x, bl1f.y);
    __half2 bl1hB = __floats2half2_rn(bl1f.z, bl1f.w);
    float4 wl2f = *(const float4*)&Wl2[4 * li];
    __half2 wl2hA = __floats2half2_rn(wl2f.x, wl2f.y);
    __half2 wl2hB = __floats2half2_rn(wl2f.z, wl2f.w);
    float4 we2v = *(const float4*)&We2[4 * li];
    float be2v = be2[0], bl2v = bl2[0];
    __half2 zero2 = __float2half2_rn(0.f);

    int e = warp * 2 + g;
    int s = 0, d = 0;
    float efl = 0.f;
    if (e < NE) {
        s = __ldg(&src[e]);
        d = __ldg(&dst[e]);
        efl = (li < 5) ? __ldg(&ef[(size_t)e * 5 + li]) : 0.f;
    }
    for (int eb = warp * 2; eb < NE; eb += 2 * nw) {
        uint4 ts = *(const uint4*)((const uint2*)&g_srct[(size_t)s * 16] + 2 * li);
        uint4 td = *(const uint4*)((const uint2*)&g_dstt[(size_t)d * 16] + 2 * li);
        __half2 efh = __float2half2_rn(efl);
        int ecur = eb + g;

        // prefetch next iteration's indices/features
        int enext = eb + 2 * nw + g;
        if (enext < NE) {
            s = __ldg(&src[enext]);
            d = __ldg(&dst[enext]);
            efl = (li < 5) ? __ldg(&ef[(size_t)enext * 5 + li]) : 0.f;
        }

        // table sums (short chain 1)
        __half2 tA  = __hadd2(__hadd2(*(__half2*)&ts.x, *(__half2*)&td.x), be1hA);
        __half2 tB  = __hadd2(__hadd2(*(__half2*)&ts.z, *(__half2*)&td.z), be1hB);
        __half2 tvA = __hadd2(*(__half2*)&ts.y, *(__half2*)&td.y);
        __half2 tvB = __hadd2(*(__half2*)&ts.w, *(__half2*)&td.w);

        // ef x W chains (short chain 2), seeded by hmul2
        unsigned int efu = *(unsigned int*)&efh;
        unsigned int eku = __shfl_sync(0xffffffffu, efu, base);
        __half2 ekh = *(__half2*)&eku;
        __half2 cA = __hmul2(ekh, wehA[0]);
        __half2 cB = __hmul2(ekh, wehB[0]);
        __half2 dA = __hmul2(ekh, wlhA[0]);
        __half2 dB = __hmul2(ekh, wlhB[0]);
#pragma unroll
        for (int k = 1; k < 5; k++) {
            eku = __shfl_sync(0xffffffffu, efu, base + k);
            ekh = *(__half2*)&eku;
            cA = __hfma2(ekh, wehA[k], cA);
            cB = __hfma2(ekh, wehB[k], cB);
            dA = __hfma2(ekh, wlhA[k], dA);
            dB = __hfma2(ekh, wlhB[k], dB);
        }
        // u-path: combine chains in fp32, tanh + We2 dot in fp32
        float2 tAf = __half22float2(tA), cAf = __half22float2(cA);
        float2 tBf = __half22float2(tB), cBf = __half22float2(cB);
        float u0x = tAf.x + cAf.x, u0y = tAf.y + cAf.y;
        float u1x = tBf.x + cBf.x, u1y = tBf.y + cBf.y;
        float part = tanh_fast(u0x) * we2v.x + tanh_fast(u0y) * we2v.y
                   + tanh_fast(u1x) * we2v.z + tanh_fast(u1y) * we2v.w;
#pragma unroll
        for (int o = 8; o > 0; o >>= 1) part += __shfl_xor_sync(0xffffffffu, part, o);
        float wgt = 1.f / (1.f + __expf(-(part + be2v)));

        // v-path epilogue in half2
        __half2 wgt2 = __float2half2_rn(wgt);
        __half2 vA = __hadd2(tvA, dA);
        __half2 vB = __hadd2(tvB, dB);
        __half2 oA = __hmax2(__hfma2(wgt2, vA, bl1hA), zero2);
        __half2 oB = __hmax2(__hfma2(wgt2, vB, bl1hB), zero2);
        __half2 pd = __hfma2(oB, wl2hB, __hmul2(oA, wl2hA));
        float2 pdf = __half22float2(pd);
        float p2 = pdf.x + pdf.y;
#pragma unroll
        for (int o = 8; o > 0; o >>= 1) p2 += __shfl_xor_sync(0xffffffffu, p2, o);
        if (li == 0) out[ecur] = p2 + bl2v;
    }
}

// ---------------- launch -----------------------------------------------------
extern "C" void kernel_launch(void* const* d_in, const int* in_sizes, int n_in,
                              void* d_out, int out_size) {
    const float* node_feat = (const float*)d_in[0];
    const float* edge_feat = (const float*)d_in[1];
    const int*   src       = (const int*)d_in[2];
    const int*   dst       = (const int*)d_in[3];
    const float* W1s = (const float*)d_in[4];
    const float* W1n = (const float*)d_in[5];
    const float* b1  = (const float*)d_in[6];
    const float* W2s = (const float*)d_in[7];
    const float* W2n = (const float*)d_in[8];
    const float* b2  = (const float*)d_in[9];
    const float* Wnp = (const float*)d_in[10];
    const float* bnp = (const float*)d_in[11];
    const float* We1 = (const float*)d_in[12];
    const float* be1 = (const float*)d_in[13];
    const float* We2 = (const float*)d_in[14];
    const float* be2 = (const float*)d_in[15];
    const float* Wl1 = (const float*)d_in[16];
    const float* bl1 = (const float*)d_in[17];
    const float* Wl2 = (const float*)d_in[18];
    const float* bl2 = (const float*)d_in[19];
    float* out = (float*)d_out;

    float *ph1, *ph2;
    void *pst, *pdt, *pdc;
    cudaGetSymbolAddress((void**)&ph1, g_h1);
    cudaGetSymbolAddress((void**)&ph2, g_h2);
    cudaGetSymbolAddress(&pst, g_srct);
    cudaGetSymbolAddress(&pdt, g_dstt);
    cudaGetSymbolAddress(&pdc, g_dc);

    int nb   = (NN + 1023) / 1024;
    int nblk = (NN + 7) / 8;          // warp-per-node kernels
    int wblk = (NN + 127) / 128;      // WMMA kernels (128 nodes/block)

    cudaMemsetAsync(pdc, 0, 2 * NN * sizeof(int));
    k_deg<<<(NE + 255) / 256, 256>>>(dst);
    k_scan1<<<nb, 1024>>>();
    k_scan2<<<1, 128>>>(nb);
    k_scan3<<<(NN + 255) / 256, 256>>>();
    k_scatter<<<(NE + 255) / 256, 256>>>(src, dst);

    // Layer 1
    k_proj1<<<(NN * 32 + 255) / 256, 256>>>(node_feat, W1n);
    k_sage1<<<nblk, 256>>>(node_feat, W1s, b1);

    // Layer 2: p2 = h1@W2n (half2) AND h1@W2s (fp32) via WMMA, then combine
    k_wdual<<<wblk, 256>>>(ph1, W2n, W2s, ph2);
    k_sage2b<<<nblk, 256>>>(b2);

    // fused: hp = relu(h2@Wnp+bnp) in smem, then both role tables
    k_wfuse<<<wblk, 256>>>(ph2, Wnp, bnp, We1, Wl1,
                           (unsigned int*)pst, (unsigned int*)pdt);

    // persistent fused edge stage
    k_edge<<<1184, 256>>>(src, dst, edge_feat,
                          We1, be1, We2, be2, Wl1, bl1, Wl2, bl2, out);
}